// round 7
// baseline (speedup 1.0000x reference)
#include <cuda_runtime.h>
#include <cuda_bf16.h>
#include <math.h>
#include <cstdint>

// Problem constants
#define Bn 2
#define Cc 2
#define Ff 1024
#define Ww 1024
#define Hh 4
#define Dd 256
#define EF 4096
#define Ll 15
#define NBn 3
#define BC 4              // B*C
#define FW (Ff*Ww)        // 1048576
#define WW (Ww*Ww)        // 1048576

// ---------------- scratch (device globals; no allocations) ----------------
__device__ float g_h [BC*FW];
__device__ float g_t0[BC*FW];
__device__ float g_t1[BC*FW];
__device__ float g_s [16*WW];                 // attention scores fp32 [bc,h,Wq,Wk]

__device__ __nv_bfloat16 g_hTh[BC*FW], g_hTl[BC*FW];   // [bc,W,F] transposed activations
__device__ __nv_bfloat16 g_qTh[BC*FW], g_qTl[BC*FW];   // [bc,W,F] (reused for attnT)
__device__ __nv_bfloat16 g_kTh[BC*FW], g_kTl[BC*FW];
__device__ __nv_bfloat16 g_vh [BC*FW], g_vl [BC*FW];   // V [bc,F,W]
__device__ __nv_bfloat16 g_sh [16*WW], g_sl [16*WW];   // softmax out bf16 split
__device__ __nv_bfloat16 g_uTh[(size_t)BC*Ww*EF], g_uTl[(size_t)BC*Ww*EF]; // [bc,W,EF]
__device__ __nv_bfloat16 g_wh [(size_t)Cc*EF*Ff], g_wl[(size_t)Cc*EF*Ff];  // weight split scratch

__device__ __forceinline__ float gelu_f(float x) {
    return 0.5f * x * (1.0f + erff(x * 0.70710678118654752f));
}
__device__ __forceinline__ void split2(float v, __nv_bfloat16& h, __nv_bfloat16& l){
    h = __float2bfloat16(v);
    l = __float2bfloat16(v - __bfloat162float(h));
}

// ================= async-copy / mma.sync helpers =================
__device__ __forceinline__ uint32_t s2u(const void* p){
    uint32_t a;
    asm("{ .reg .u64 t; cvta.to.shared.u64 t, %1; cvt.u32.u64 %0, t; }" : "=r"(a) : "l"(p));
    return a;
}
__device__ __forceinline__ void cpa16(uint32_t dst, const void* src){
    asm volatile("cp.async.cg.shared.global [%0], [%1], 16;" :: "r"(dst), "l"(src));
}
__device__ __forceinline__ void cpa_commit(){ asm volatile("cp.async.commit_group;" ::: "memory"); }
template<int N> __device__ __forceinline__ void cpa_wait(){
    asm volatile("cp.async.wait_group %0;" :: "n"(N) : "memory");
}
__device__ __forceinline__ void ldm4(uint32_t& r0, uint32_t& r1, uint32_t& r2, uint32_t& r3, uint32_t a){
    asm volatile("ldmatrix.sync.aligned.m8n8.x4.shared.b16 {%0,%1,%2,%3}, [%4];"
                 : "=r"(r0), "=r"(r1), "=r"(r2), "=r"(r3) : "r"(a));
}
__device__ __forceinline__ void mma16816(float* c,
    uint32_t a0, uint32_t a1, uint32_t a2, uint32_t a3, uint32_t b0, uint32_t b1){
    asm volatile(
        "mma.sync.aligned.m16n8k16.row.col.f32.bf16.bf16.f32 "
        "{%0,%1,%2,%3}, {%4,%5,%6,%7}, {%8,%9}, {%0,%1,%2,%3};"
        : "+f"(c[0]), "+f"(c[1]), "+f"(c[2]), "+f"(c[3])
        : "r"(a0), "r"(a1), "r"(a2), "r"(a3), "r"(b0), "r"(b1));
}

// ================= split-bf16 tensor-core GEMM (mma.sync) =================
// C[m,n] = scale * sum_k A(m,k)*B(n,k) (+bias[m]) (optional GELU)
// OUT=0: fp32 to Cg.  OUT=1: bf16 hi/lo to CH/CL, same layout.
// OUT=2: bf16 hi/lo TRANSPOSED (CT[n, m]) to CH/CL via smem-staged transpose.
#define KC 64
#define STG_BYTES 65536u       // Ah 16K | Al 16K | Bh 16K | Bl 16K
#define TG_SMEM 132096         // 2 stages + 1K alignment slack

__device__ __forceinline__ void load_tiles(
    uint32_t sb,
    const __nv_bfloat16* pAh, const __nv_bfloat16* pAl,
    const __nv_bfloat16* pBh, const __nv_bfloat16* pBl,
    int m0, int n0, int k0, int lda, int ldb, int tid)
{
    #pragma unroll
    for (int it = 0; it < 4; it++) {
        const int slot = tid + it*256;          // 0..1023 : 128 rows x 8 chunks
        const int r = slot >> 3, c = slot & 7;
        const uint32_t sw = (uint32_t)(r*128) + (uint32_t)((c ^ (r & 7)) * 16);
        const long long ga = (long long)(m0 + r)*lda + k0 + c*8;
        const long long gb = (long long)(n0 + r)*ldb + k0 + c*8;
        cpa16(sb +     0 + sw, pAh + ga);
        cpa16(sb + 16384 + sw, pAl + ga);
        cpa16(sb + 32768 + sw, pBh + gb);
        cpa16(sb + 49152 + sw, pBl + gb);
    }
}

template<int DOGELU, int HASBIAS, int OUT>
__global__ __launch_bounds__(256, 1) void tgemm_k(
    const __nv_bfloat16* __restrict__ Agh, const __nv_bfloat16* __restrict__ Agl,
    const __nv_bfloat16* __restrict__ Bgh, const __nv_bfloat16* __restrict__ Bgl,
    float* __restrict__ Cg, const float* __restrict__ biasg,
    __nv_bfloat16* __restrict__ CH, __nv_bfloat16* __restrict__ CL,
    int K, int lda, int ldb, int ldc, int heads, int aMod,
    long long aSB, long long aSH, long long bSB, long long bSH,
    long long cSB, long long cSH, long long biasSB, float scale)
{
    extern __shared__ char dsm[];
    char* ap = (char*)(((uintptr_t)dsm + 1023) & ~(uintptr_t)1023);
    const uint32_t base = s2u(ap);
    const int tid = threadIdx.x;
    const int lane = tid & 31;
    const int wid = tid >> 5;
    const int wm = wid >> 2, wn = wid & 3;      // 2 x 4 warp grid, warp tile 64x32

    const int z = blockIdx.z, bb = z / heads, hh = z % heads;
    const __nv_bfloat16* pAh = Agh + (long long)(bb % aMod)*aSB + (long long)hh*aSH;
    const __nv_bfloat16* pAl = Agl + (long long)(bb % aMod)*aSB + (long long)hh*aSH;
    const __nv_bfloat16* pBh = Bgh + (long long)bb*bSB + (long long)hh*bSH;
    const __nv_bfloat16* pBl = Bgl + (long long)bb*bSB + (long long)hh*bSH;
    const long long cOff = (long long)bb*cSB + (long long)hh*cSH;
    const int m0 = blockIdx.y * 128;
    const int n0 = blockIdx.x * 128;

    float acc[4][4][4];
    #pragma unroll
    for (int i = 0; i < 4; i++)
        #pragma unroll
        for (int j = 0; j < 4; j++)
            #pragma unroll
            for (int r = 0; r < 4; r++) acc[i][j][r] = 0.f;

    const int NC = K / KC;
    load_tiles(base, pAh, pAl, pBh, pBl, m0, n0, 0, lda, ldb, tid);
    cpa_commit();
    if (NC > 1) {
        load_tiles(base + STG_BYTES, pAh, pAl, pBh, pBl, m0, n0, KC, lda, ldb, tid);
        cpa_commit();
    }

    #pragma unroll 1
    for (int c = 0; c < NC; c++) {
        const int s = c & 1;
        const uint32_t sb = base + (uint32_t)s * STG_BYTES;
        if (c + 1 < NC) cpa_wait<1>(); else cpa_wait<0>();
        __syncthreads();

        #pragma unroll
        for (int kk = 0; kk < 4; kk++) {        // 4 k16 steps per 64-chunk
            const int colc = kk*2 + (lane >> 4);
            uint32_t ah[4][4], al[4][4];
            #pragma unroll
            for (int mt = 0; mt < 4; mt++) {
                const int r = wm*64 + mt*16 + (lane & 15);
                const uint32_t ad = sb + (uint32_t)(r*128) + (uint32_t)((colc ^ (r & 7)) * 16);
                ldm4(ah[mt][0], ah[mt][1], ah[mt][2], ah[mt][3], ad);
                ldm4(al[mt][0], al[mt][1], al[mt][2], al[mt][3], ad + 16384);
            }
            uint32_t bh[2][4], bl[2][4];
            #pragma unroll
            for (int nt = 0; nt < 2; nt++) {
                const int r = wn*32 + nt*16 + (lane & 15);
                const uint32_t bd = sb + 32768 + (uint32_t)(r*128) + (uint32_t)((colc ^ (r & 7)) * 16);
                ldm4(bh[nt][0], bh[nt][1], bh[nt][2], bh[nt][3], bd);
                ldm4(bl[nt][0], bl[nt][1], bl[nt][2], bl[nt][3], bd + 16384);
            }
            #pragma unroll
            for (int mt = 0; mt < 4; mt++) {
                #pragma unroll
                for (int n8 = 0; n8 < 4; n8++) {
                    const int nt = n8 >> 1, j = n8 & 1;
                    float* cc = acc[mt][n8];
                    mma16816(cc, ah[mt][0], ah[mt][1], ah[mt][2], ah[mt][3], bh[nt][j], bh[nt][j+2]);
                    mma16816(cc, ah[mt][0], ah[mt][1], ah[mt][2], ah[mt][3], bl[nt][j], bl[nt][j+2]);
                    mma16816(cc, al[mt][0], al[mt][1], al[mt][2], al[mt][3], bh[nt][j], bh[nt][j+2]);
                }
            }
        }
        __syncthreads();
        if (c + 2 < NC) {
            load_tiles(base + (uint32_t)s * STG_BYTES, pAh, pAl, pBh, pBl,
                       m0, n0, (c + 2) * KC, lda, ldb, tid);
            cpa_commit();
        }
    }

    const float* bp = HASBIAS ? (biasg + (long long)(bb % aMod)*biasSB) : nullptr;

    if (OUT == 2) {
        // stage fp32 tile in smem (pad 129), then write bf16 hi/lo transposed
        float* tb = (float*)ap;
        #pragma unroll
        for (int mt = 0; mt < 4; mt++) {
            const int lr0 = wm*64 + mt*16 + (lane >> 2);
            const int lr1 = lr0 + 8;
            const float bv0 = HASBIAS ? bp[m0 + lr0] : 0.f;
            const float bv1 = HASBIAS ? bp[m0 + lr1] : 0.f;
            #pragma unroll
            for (int n8 = 0; n8 < 4; n8++) {
                const int cn = wn*32 + n8*8 + (lane & 3)*2;
                float v0 = acc[mt][n8][0]*scale + bv0;
                float v1 = acc[mt][n8][1]*scale + bv0;
                float v2 = acc[mt][n8][2]*scale + bv1;
                float v3 = acc[mt][n8][3]*scale + bv1;
                if (DOGELU) { v0 = gelu_f(v0); v1 = gelu_f(v1); v2 = gelu_f(v2); v3 = gelu_f(v3); }
                tb[lr0*129 + cn] = v0; tb[lr0*129 + cn + 1] = v1;
                tb[lr1*129 + cn] = v2; tb[lr1*129 + cn + 1] = v3;
            }
        }
        __syncthreads();
        const int n = tid >> 1, mh = (tid & 1) * 64;
        __nv_bfloat16* ph = CH + cOff + (long long)(n0 + n)*ldc + m0 + mh;
        __nv_bfloat16* pl = CL + cOff + (long long)(n0 + n)*ldc + m0 + mh;
        #pragma unroll
        for (int j = 0; j < 64; j += 2) {
            __nv_bfloat162 h2, l2;
            split2(tb[(mh + j)*129 + n],     h2.x, l2.x);
            split2(tb[(mh + j + 1)*129 + n], h2.y, l2.y);
            *(__nv_bfloat162*)(ph + j) = h2;
            *(__nv_bfloat162*)(pl + j) = l2;
        }
        return;
    }

    #pragma unroll
    for (int mt = 0; mt < 4; mt++) {
        const int r0 = m0 + wm*64 + mt*16 + (lane >> 2);
        const int r1 = r0 + 8;
        const float bv0 = HASBIAS ? bp[r0] : 0.f;
        const float bv1 = HASBIAS ? bp[r1] : 0.f;
        #pragma unroll
        for (int n8 = 0; n8 < 4; n8++) {
            const int cn = n0 + wn*32 + n8*8 + (lane & 3)*2;
            float v0 = acc[mt][n8][0]*scale + bv0;
            float v1 = acc[mt][n8][1]*scale + bv0;
            float v2 = acc[mt][n8][2]*scale + bv1;
            float v3 = acc[mt][n8][3]*scale + bv1;
            if (DOGELU) { v0 = gelu_f(v0); v1 = gelu_f(v1); v2 = gelu_f(v2); v3 = gelu_f(v3); }
            if (OUT == 0) {
                float* Cp = Cg + cOff;
                *(float2*)&Cp[(long long)r0*ldc + cn] = make_float2(v0, v1);
                *(float2*)&Cp[(long long)r1*ldc + cn] = make_float2(v2, v3);
            } else {
                __nv_bfloat162 h0, l0, h1, l1;
                split2(v0, h0.x, l0.x); split2(v1, h0.y, l0.y);
                split2(v2, h1.x, l1.x); split2(v3, h1.y, l1.y);
                *(__nv_bfloat162*)&CH[cOff + (long long)r0*ldc + cn] = h0;
                *(__nv_bfloat162*)&CL[cOff + (long long)r0*ldc + cn] = l0;
                *(__nv_bfloat162*)&CH[cOff + (long long)r1*ldc + cn] = h1;
                *(__nv_bfloat162*)&CL[cOff + (long long)r1*ldc + cn] = l1;
            }
        }
    }
}

// ================= fp32 -> bf16 hi/lo splits =================
__global__ __launch_bounds__(256) void split_k(
    const float* __restrict__ x, __nv_bfloat16* __restrict__ oh,
    __nv_bfloat16* __restrict__ ol, int n4)
{
    const int i = blockIdx.x * 256 + threadIdx.x;
    if (i >= n4) return;
    const float4 v = ((const float4*)x)[i];
    __nv_bfloat162 h0, h1, l0, l1;
    split2(v.x, h0.x, l0.x); split2(v.y, h0.y, l0.y);
    split2(v.z, h1.x, l1.x); split2(v.w, h1.y, l1.y);
    ((__nv_bfloat162*)oh)[i*2]   = h0; ((__nv_bfloat162*)oh)[i*2+1] = h1;
    ((__nv_bfloat162*)ol)[i*2]   = l0; ((__nv_bfloat162*)ol)[i*2+1] = l1;
}

// transpose+split: in [bc, R, W] fp32 -> out [bc, W, R] bf16 hi/lo
__global__ __launch_bounds__(256) void splitT_k(
    const float* __restrict__ x, __nv_bfloat16* __restrict__ oh,
    __nv_bfloat16* __restrict__ ol, int R)
{
    __shared__ float t[32][33];
    const int bc = blockIdx.z;
    const int w0 = blockIdx.x * 32, r0 = blockIdx.y * 32;
    const int tx = threadIdx.x, ty = threadIdx.y;     // (32,8)
    const float* xb = x + (size_t)bc * R * Ww;
    #pragma unroll
    for (int i = 0; i < 4; i++)
        t[ty + i*8][tx] = xb[(size_t)(r0 + ty + i*8) * Ww + w0 + tx];
    __syncthreads();
    __nv_bfloat16* ohb = oh + (size_t)bc * Ww * R;
    __nv_bfloat16* olb = ol + (size_t)bc * Ww * R;
    #pragma unroll
    for (int i = 0; i < 4; i++) {
        const float v = t[tx][ty + i*8];
        __nv_bfloat16 h, l; split2(v, h, l);
        const size_t o = (size_t)(w0 + ty + i*8) * R + r0 + tx;
        ohb[o] = h; olb[o] = l;
    }
}

// ---------------- fused conv1x7 + RoPE + transpose-split (Q/K path) ----------------
// in: x [b*2, F, W] fp32 ; out: oh/ol [b*2, W, F] bf16 hi/lo
// grid (W/32, F/32, Bn), block (32,8)
__global__ __launch_bounds__(256) void convrope_k(
    const float* __restrict__ x, __nv_bfloat16* __restrict__ oh,
    __nv_bfloat16* __restrict__ ol,
    const float* __restrict__ wt, const float* __restrict__ bs)
{
    __shared__ float xin[2][32][40];
    __shared__ float cv[2][32][33];
    const int b = blockIdx.z;
    const int w0 = blockIdx.x*32, f0 = blockIdx.y*32;
    const int tx = threadIdx.x, ty = threadIdx.y;
    const int tid = ty*32 + tx;

    for (int i = tid; i < 2*32*38; i += 256) {
        const int ci = i / (32*38), rem = i % (32*38);
        const int fi = rem / 38, wi = rem % 38;
        const int wg = w0 + wi - 3;
        xin[ci][fi][wi] = ((unsigned)wg < (unsigned)Ww)
            ? x[((size_t)(b*2 + ci)*Ff + f0 + fi)*Ww + wg] : 0.f;
    }
    __syncthreads();

    float wreg[2][2][7];
    #pragma unroll
    for (int co = 0; co < 2; co++)
        #pragma unroll
        for (int ci = 0; ci < 2; ci++)
            #pragma unroll
            for (int j = 0; j < 7; j++)
                wreg[co][ci][j] = wt[(co*2 + ci)*7 + j];
    const float b0 = bs[0], b1 = bs[1];

    #pragma unroll
    for (int r = 0; r < 4; r++) {
        const int fi = ty*4 + r;
        float a0 = b0, a1 = b1;
        #pragma unroll
        for (int ci = 0; ci < 2; ci++)
            #pragma unroll
            for (int j = 0; j < 7; j++) {
                const float xv = xin[ci][fi][tx + j];
                a0 = fmaf(xv, wreg[0][ci][j], a0);
                a1 = fmaf(xv, wreg[1][ci][j], a1);
            }
        cv[0][fi][tx] = a0; cv[1][fi][tx] = a1;
    }
    __syncthreads();

    // rope + split + transposed write: thread -> (co, w, 8 f)
    const int co = tid >> 7, wl = (tid >> 2) & 31, fq = (tid & 3) * 8;
    const int wg = w0 + wl;
    uint4 hv, lv;
    __nv_bfloat16* hb = (__nv_bfloat16*)&hv;
    __nv_bfloat16* lb = (__nv_bfloat16*)&lv;
    #pragma unroll
    for (int p = 0; p < 4; p++) {
        const int fl = fq + p*2;
        const float x0 = cv[co][fl][wl], x1 = cv[co][fl + 1][wl];
        const int fg = f0 + fl;
        const int ttp = (fg >> 1) & 127;
        const float inv = expf(-(float)ttp * (9.2103403719761836f / 128.f));
        float sn, cn; sincosf((float)wg * inv, &sn, &cn);
        const float y0 = x0*cn - x1*sn;
        const float y1 = x1*cn + x0*sn;
        split2(y0, hb[p*2],   lb[p*2]);
        split2(y1, hb[p*2+1], lb[p*2+1]);
    }
    const size_t o = ((size_t)(b*2 + co)*Ww + wg)*Ff + f0 + fq;
    *(uint4*)(oh + o) = hv;
    *(uint4*)(ol + o) = lv;
}

// ---------------- fused conv1x7 + split (V path), layout preserved ----------------
__global__ __launch_bounds__(256) void convsplit_k(
    const float* __restrict__ x, __nv_bfloat16* __restrict__ oh,
    __nv_bfloat16* __restrict__ ol,
    const float* __restrict__ wt, const float* __restrict__ bs)
{
    const int t = blockIdx.x * 256 + threadIdx.x;
    const int wc = t & 1023;
    const int f  = (t >> 10) & 1023;
    const int co = (t >> 20) & 1;
    const int bb = t >> 21;
    float s = bs[co];
    #pragma unroll
    for (int ci = 0; ci < Cc; ci++) {
        const float* row = x + ((size_t)(bb*Cc + ci) * Ff + f) * Ww;
        const float* wp  = wt + (co*Cc + ci) * 7;
        #pragma unroll
        for (int j = 0; j < 7; j++) {
            const int ww = wc + j - 3;
            if ((unsigned)ww < (unsigned)Ww) s = fmaf(row[ww], wp[j], s);
        }
    }
    __nv_bfloat16 h, l; split2(s, h, l);
    oh[t] = h; ol[t] = l;
}

// ---------------- conv 3x3 (pad 1), optional GELU ----------------
__global__ __launch_bounds__(256) void conv3x3_k(
    const float* __restrict__ x, float* __restrict__ y,
    const float* __restrict__ wt, const float* __restrict__ bs, int dogelu)
{
    const int t = blockIdx.x * 256 + threadIdx.x;
    const int wc = t & 1023;
    const int f  = (t >> 10) & 1023;
    const int co = (t >> 20) & 1;
    const int bb = t >> 21;
    float s = bs[co];
    #pragma unroll
    for (int ci = 0; ci < Cc; ci++) {
        const float* xp = x + ((size_t)(bb*Cc + ci)) * FW;
        const float* wp = wt + (co*Cc + ci) * 9;
        #pragma unroll
        for (int ky = 0; ky < 3; ky++) {
            const int ff = f + ky - 1;
            if ((unsigned)ff < (unsigned)Ff) {
                const float* row = xp + (size_t)ff * Ww;
                #pragma unroll
                for (int kx = 0; kx < 3; kx++) {
                    const int ww = wc + kx - 1;
                    if ((unsigned)ww < (unsigned)Ww) s = fmaf(row[ww], wp[ky*3+kx], s);
                }
            }
        }
    }
    if (dogelu) s = gelu_f(s);
    y[t] = s;
}

// ---------------- row softmax -> bf16 hi/lo ----------------
__global__ __launch_bounds__(256) void softmax_k(
    const float* __restrict__ sp, __nv_bfloat16* __restrict__ oh,
    __nv_bfloat16* __restrict__ ol)
{
    const size_t row = blockIdx.x;
    const float* p = sp + row * Ww;
    const int t = threadIdx.x, lane = t & 31, wid = t >> 5;
    float4 v = ((const float4*)p)[t];
    float mx = fmaxf(fmaxf(v.x, v.y), fmaxf(v.z, v.w));
    #pragma unroll
    for (int o = 16; o > 0; o >>= 1) mx = fmaxf(mx, __shfl_xor_sync(0xffffffffu, mx, o));
    __shared__ float red[8];
    if (lane == 0) red[wid] = mx;
    __syncthreads();
    mx = red[0];
    #pragma unroll
    for (int i = 1; i < 8; i++) mx = fmaxf(mx, red[i]);
    __syncthreads();
    v.x = expf(v.x - mx); v.y = expf(v.y - mx); v.z = expf(v.z - mx); v.w = expf(v.w - mx);
    float sm = v.x + v.y + v.z + v.w;
    #pragma unroll
    for (int o = 16; o > 0; o >>= 1) sm += __shfl_xor_sync(0xffffffffu, sm, o);
    if (lane == 0) red[wid] = sm;
    __syncthreads();
    sm = red[0]+red[1]+red[2]+red[3]+red[4]+red[5]+red[6]+red[7];
    const float r = 1.f / sm;
    v.x *= r; v.y *= r; v.z *= r; v.w *= r;
    __nv_bfloat162 h0, h1, l0, l1;
    split2(v.x, h0.x, l0.x); split2(v.y, h0.y, l0.y);
    split2(v.z, h1.x, l1.x); split2(v.w, h1.y, l1.y);
    ((__nv_bfloat162*)(oh + row*Ww))[t*2]   = h0;
    ((__nv_bfloat162*)(oh + row*Ww))[t*2+1] = h1;
    ((__nv_bfloat162*)(ol + row*Ww))[t*2]   = l0;
    ((__nv_bfloat162*)(ol + row*Ww))[t*2+1] = l1;
}

// ---------------- residual + LayerNorm over F, h <- LN(h+z), smem value cache ----------------
__global__ __launch_bounds__(512) void lnres_k(
    float* __restrict__ h, const float* __restrict__ z,
    const float* __restrict__ g, const float* __restrict__ b)
{
    extern __shared__ float val[];                  // [1024][32]
    const int tx = threadIdx.x, ty = threadIdx.y;
    const int wc = blockIdx.x * 32 + tx;
    const int bc = blockIdx.y;
    const int c  = bc & 1;
    float* hp = h + (size_t)bc * FW + wc;
    const float* zp = z + (size_t)bc * FW + wc;
    float sum = 0.f, sq = 0.f;
    for (int f = ty; f < Ff; f += 16) {
        const float v = hp[(size_t)f * Ww] + zp[(size_t)f * Ww];
        val[f*32 + tx] = v;
        sum += v; sq += v * v;
    }
    __shared__ float s1[16][32], s2[16][32];
    __shared__ float smu[32], srs[32];
    s1[ty][tx] = sum; s2[ty][tx] = sq;
    __syncthreads();
    if (ty == 0) {
        float a = 0.f, q = 0.f;
        #pragma unroll
        for (int r = 0; r < 16; r++) { a += s1[r][tx]; q += s2[r][tx]; }
        const float mu = a * (1.f / Ff);
        const float var = q * (1.f / Ff) - mu * mu;
        smu[tx] = mu; srs[tx] = rsqrtf(var + 1e-5f);
    }
    __syncthreads();
    const float mu = smu[tx], rs = srs[tx];
    for (int f = ty; f < Ff; f += 16) {
        const float v = val[f*32 + tx];
        hp[(size_t)f * Ww] = (v - mu) * rs * g[c*Ff + f] + b[c*Ff + f];
    }
}

// ---------------- 2-channel mix (1x1 conv / output projection) ----------------
__global__ __launch_bounds__(256) void chanmix_k(
    const float* __restrict__ in, float* __restrict__ out,
    const float* __restrict__ m, const float* __restrict__ bs)
{
    const int t = blockIdx.x * 256 + threadIdx.x;
    const int pos = t & (FW - 1);
    const int co  = (t >> 20) & 1;
    const int bb  = t >> 21;
    float s = bs ? bs[co] : 0.f;
    s = fmaf(in[(size_t)(bb*Cc + 0) * FW + pos], m[co*Cc + 0], s);
    s = fmaf(in[(size_t)(bb*Cc + 1) * FW + pos], m[co*Cc + 1], s);
    out[t] = s;
}

// ---------------- launch ----------------
extern "C" void kernel_launch(void* const* d_in, const int* in_sizes, int n_in,
                              void* d_out, int out_size)
{
    (void)in_sizes; (void)n_in; (void)out_size;
    const float* x       = (const float*)d_in[0];
    const float* enc_c1w = (const float*)d_in[1];
    const float* enc_c1b = (const float*)d_in[2];
    const float* enc_c2w = (const float*)d_in[3];
    const float* enc_c2b = (const float*)d_in[4];
    const float* enc_nw  = (const float*)d_in[5];
    const float* enc_nb  = (const float*)d_in[6];
    const float* qw  = (const float*)d_in[7];
    const float* qb  = (const float*)d_in[8];
    const float* qcw = (const float*)d_in[9];
    const float* qcb = (const float*)d_in[10];
    const float* kw  = (const float*)d_in[11];
    const float* kb  = (const float*)d_in[12];
    const float* kcw = (const float*)d_in[13];
    const float* kcb = (const float*)d_in[14];
    const float* vw  = (const float*)d_in[15];
    const float* vb  = (const float*)d_in[16];
    const float* vcw = (const float*)d_in[17];
    const float* vcb = (const float*)d_in[18];
    const float* ow  = (const float*)d_in[19];
    const float* ob  = (const float*)d_in[20];
    const float* ocw = (const float*)d_in[21];
    const float* ocb = (const float*)d_in[22];
    const float* n1w = (const float*)d_in[23];
    const float* n1b = (const float*)d_in[24];
    const float* f1w = (const float*)d_in[25];
    const float* f1b = (const float*)d_in[26];
    const float* f2w = (const float*)d_in[27];
    const float* f2b = (const float*)d_in[28];
    const float* n2w = (const float*)d_in[29];
    const float* n2b = (const float*)d_in[30];
    const float* out_w = (const float*)d_in[31];

    float *h, *t0, *t1, *s;
    __nv_bfloat16 *hTh,*hTl,*qTh,*qTl,*kTh,*kTl,*vh,*vl,*sh,*sl,*uTh,*uTl,*wh,*wl;
    cudaGetSymbolAddress((void**)&h,  g_h);
    cudaGetSymbolAddress((void**)&t0, g_t0);
    cudaGetSymbolAddress((void**)&t1, g_t1);
    cudaGetSymbolAddress((void**)&s,  g_s);
    cudaGetSymbolAddress((void**)&hTh, g_hTh); cudaGetSymbolAddress((void**)&hTl, g_hTl);
    cudaGetSymbolAddress((void**)&qTh, g_qTh); cudaGetSymbolAddress((void**)&qTl, g_qTl);
    cudaGetSymbolAddress((void**)&kTh, g_kTh); cudaGetSymbolAddress((void**)&kTl, g_kTl);
    cudaGetSymbolAddress((void**)&vh,  g_vh);  cudaGetSymbolAddress((void**)&vl,  g_vl);
    cudaGetSymbolAddress((void**)&sh,  g_sh);  cudaGetSymbolAddress((void**)&sl,  g_sl);
    cudaGetSymbolAddress((void**)&uTh, g_uTh); cudaGetSymbolAddress((void**)&uTl, g_uTl);
    cudaGetSymbolAddress((void**)&wh,  g_wh);  cudaGetSymbolAddress((void**)&wl,  g_wl);

    cudaFuncSetAttribute(tgemm_k<0,1,0>, cudaFuncAttributeMaxDynamicSharedMemorySize, TG_SMEM);
    cudaFuncSetAttribute(tgemm_k<0,0,0>, cudaFuncAttributeMaxDynamicSharedMemorySize, TG_SMEM);
    cudaFuncSetAttribute(tgemm_k<0,0,1>, cudaFuncAttributeMaxDynamicSharedMemorySize, TG_SMEM);
    cudaFuncSetAttribute(tgemm_k<1,1,2>, cudaFuncAttributeMaxDynamicSharedMemorySize, TG_SMEM);
    cudaFuncSetAttribute(lnres_k, cudaFuncAttributeMaxDynamicSharedMemorySize, 131072);

    const int EW = 16384;
    const dim3 LN_G(Ww/32, BC), LN_B(32, 16);
    const int BIG = 1 << 24;
    const dim3 CR_G(Ww/32, Ff/32, Bn), CR_B(32, 8);
    const dim3 ST_B(32, 8);
    const dim3 ST_F(Ww/32, Ff/32, BC);

    cudaMemcpyAsync(h, x, sizeof(float) * (size_t)BC * FW, cudaMemcpyDeviceToDevice, 0);

    // weight-style linear (fp32 out): C[bc, M, W] = W[c, M, K] @ XT[bc, W, K]^T + bias
    auto WG = [&](const __nv_bfloat16* Ah, const __nv_bfloat16* Al,
                  const __nv_bfloat16* Bh, const __nv_bfloat16* Bl,
                  float* Cx, const float* bias, int M, int K, long long cRow) {
        dim3 grid(Ww/128, M/128, BC);
        tgemm_k<0,1,0><<<grid,256,TG_SMEM>>>(Ah, Al, Bh, Bl, Cx, bias, nullptr, nullptr,
            K, K, K, Ww, 1, Cc, (long long)M*K, 0, (long long)Ww*K, 0,
            cRow, 0, (long long)M, 1.f);
    };

    // --------- FrameEncoder: 3 ResBlocks ---------
    for (int nb = 0; nb < NBn; nb++) {
        conv3x3_k<<<EW,256>>>(h,  t0, enc_c1w + nb*Cc*Cc*9, enc_c1b + nb*Cc, 1);
        conv3x3_k<<<EW,256>>>(t0, t1, enc_c2w + nb*Cc*Cc*9, enc_c2b + nb*Cc, 0);
        lnres_k<<<LN_G,LN_B,131072>>>(h, t1, enc_nw + nb*Cc*Ff, enc_nb + nb*Cc*Ff);
    }

    // --------- Transformer layers ---------
    for (int l = 0; l < Ll; l++) {
        const long long lwF = (long long)l * Cc * Ff * Ff;
        const long long lwE = (long long)l * Cc * EF * Ff;

        splitT_k<<<ST_F,ST_B>>>(h, hTh, hTl, Ff);   // [bc,W,F]

        // Q: linear -> fused conv1x7+rope+transpose-split
        split_k<<<2048,256>>>(qw + lwF, wh, wl, Cc*Ff*Ff/4);
        WG(wh, wl, hTh, hTl, t0, qb + l*Cc*Ff, Ff, Ff, (long long)FW);
        convrope_k<<<CR_G,CR_B>>>(t0, qTh, qTl, qcw + l*Cc*Cc*7, qcb + l*Cc);
        // K
        split_k<<<2048,256>>>(kw + lwF, wh, wl, Cc*Ff*Ff/4);
        WG(wh, wl, hTh, hTl, t0, kb + l*Cc*Ff, Ff, Ff, (long long)FW);
        convrope_k<<<CR_G,CR_B>>>(t0, kTh, kTl, kcw + l*Cc*Cc*7, kcb + l*Cc);
        // V: linear -> fused conv1x7+split (layout [F,W])
        split_k<<<2048,256>>>(vw + lwF, wh, wl, Cc*Ff*Ff/4);
        WG(wh, wl, hTh, hTl, t0, vb + l*Cc*Ff, Ff, Ff, (long long)FW);
        convsplit_k<<<EW,256>>>(t0, vh, vl, vcw + l*Cc*Cc*7, vcb + l*Cc);

        // scores[z=bc*4+h, q, k] = Q[q,:] . K[k,:] / 32
        tgemm_k<0,0,0><<<dim3(Ww/128, Ww/128, 16),256,TG_SMEM>>>(
            qTh, qTl, kTh, kTl, s, nullptr, nullptr, nullptr,
            Dd, Ff, Ff, Ww, Hh, BIG,
            (long long)FW, (long long)Dd, (long long)FW, (long long)Dd,
            4LL*WW, (long long)WW, 0, 0.03125f);
        softmax_k<<<16*1024,256>>>(s, sh, sl);
        // attnT[bc, q, h*256+d] -> bf16 split directly (reuse qT buffers)
        tgemm_k<0,0,1><<<dim3(Dd/128, Ww/128, 16),256,TG_SMEM>>>(
            sh, sl, vh, vl, nullptr, nullptr, qTh, qTl,
            Ww, Ww, Ww, Ff, Hh, BIG,
            4LL*WW, (long long)WW, (long long)FW, (long long)Dd*Ww,
            (long long)FW, (long long)Dd, 0, 1.f);

        // output projection + 1x1 channel conv + residual LN
        split_k<<<2048,256>>>(ow + lwF, wh, wl, Cc*Ff*Ff/4);
        WG(wh, wl, qTh, qTl, t1, ob + l*Cc*Ff, Ff, Ff, (long long)FW);
        chanmix_k<<<EW,256>>>(t1, t0, ocw + l*Cc*Cc, ocb + l*Cc);
        lnres_k<<<LN_G,LN_B,131072>>>(h, t0, n1w + l*Cc*Ff, n1b + l*Cc*Ff);

        // FFN: f1 writes transposed bf16 split directly (OUT=2, GELU)
        splitT_k<<<ST_F,ST_B>>>(h, hTh, hTl, Ff);
        split_k<<<8192,256>>>(f1w + lwE, wh, wl, Cc*EF*Ff/4);
        tgemm_k<1,1,2><<<dim3(Ww/128, EF/128, BC),256,TG_SMEM>>>(
            wh, wl, hTh, hTl, nullptr, f1b + l*Cc*EF, uTh, uTl,
            Ff, Ff, Ff, EF, 1, Cc,
            (long long)EF*Ff, 0, (long long)Ww*Ff, 0,
            (long long)Ww*EF, 0, (long long)EF, 1.f);
        split_k<<<8192,256>>>(f2w + lwE, wh, wl, Cc*Ff*EF/4);
        WG(wh, wl, uTh, uTl, t0, f2b + l*Cc*Ff, Ff, EF, (long long)FW);
        lnres_k<<<LN_G,LN_B,131072>>>(h, t0, n2w + l*Cc*Ff, n2b + l*Cc*Ff);
    }

    // --------- output channel mix ---------
    chanmix_k<<<EW,256>>>(h, (float*)d_out, out_w, nullptr);
}

// round 9
// speedup vs baseline: 1.0412x; 1.0412x over previous
#include <cuda_runtime.h>
#include <cuda_bf16.h>
#include <math.h>
#include <cstdint>

// Problem constants
#define Bn 2
#define Cc 2
#define Ff 1024
#define Ww 1024
#define Hh 4
#define Dd 256
#define EF 4096
#define Ll 15
#define NBn 3
#define BC 4              // B*C
#define FW (Ff*Ww)        // 1048576
#define WW (Ww*Ww)        // 1048576

// ---------------- scratch (device globals; no allocations) ----------------
__device__ float g_h [BC*FW];
__device__ float g_t0[BC*FW];
__device__ float g_t1[BC*FW];
__device__ float g_s [16*WW];                 // attention scores fp32 [bc,h,Wq,Wk]

__device__ __nv_bfloat16 g_hTh[BC*FW], g_hTl[BC*FW];   // [bc,W,F] transposed activations
__device__ __nv_bfloat16 g_qTh[BC*FW], g_qTl[BC*FW];   // [bc,W,F] (reused for attnT)
__device__ __nv_bfloat16 g_kTh[BC*FW], g_kTl[BC*FW];
__device__ __nv_bfloat16 g_vh [BC*FW], g_vl [BC*FW];   // V [bc,F,W]
__device__ __nv_bfloat16 g_sh [16*WW], g_sl [16*WW];   // softmax out bf16 split
__device__ __nv_bfloat16 g_uTh[(size_t)BC*Ww*EF], g_uTl[(size_t)BC*Ww*EF]; // [bc,W,EF]
__device__ __nv_bfloat16 g_wh [(size_t)Cc*EF*Ff], g_wl[(size_t)Cc*EF*Ff];  // weight split scratch

__device__ __forceinline__ float gelu_f(float x) {
    return 0.5f * x * (1.0f + erff(x * 0.70710678118654752f));
}
__device__ __forceinline__ void split2(float v, __nv_bfloat16& h, __nv_bfloat16& l){
    h = __float2bfloat16(v);
    l = __float2bfloat16(v - __bfloat162float(h));
}

// ================= async-copy / mma.sync helpers =================
__device__ __forceinline__ uint32_t s2u(const void* p){
    uint32_t a;
    asm("{ .reg .u64 t; cvta.to.shared.u64 t, %1; cvt.u32.u64 %0, t; }" : "=r"(a) : "l"(p));
    return a;
}
__device__ __forceinline__ void cpa16(uint32_t dst, const void* src){
    asm volatile("cp.async.cg.shared.global [%0], [%1], 16;" :: "r"(dst), "l"(src));
}
__device__ __forceinline__ void cpa_commit(){ asm volatile("cp.async.commit_group;" ::: "memory"); }
template<int N> __device__ __forceinline__ void cpa_wait(){
    asm volatile("cp.async.wait_group %0;" :: "n"(N) : "memory");
}
__device__ __forceinline__ void ldm4(uint32_t& r0, uint32_t& r1, uint32_t& r2, uint32_t& r3, uint32_t a){
    asm volatile("ldmatrix.sync.aligned.m8n8.x4.shared.b16 {%0,%1,%2,%3}, [%4];"
                 : "=r"(r0), "=r"(r1), "=r"(r2), "=r"(r3) : "r"(a));
}
__device__ __forceinline__ void mma16816(float* c,
    uint32_t a0, uint32_t a1, uint32_t a2, uint32_t a3, uint32_t b0, uint32_t b1){
    asm volatile(
        "mma.sync.aligned.m16n8k16.row.col.f32.bf16.bf16.f32 "
        "{%0,%1,%2,%3}, {%4,%5,%6,%7}, {%8,%9}, {%0,%1,%2,%3};"
        : "+f"(c[0]), "+f"(c[1]), "+f"(c[2]), "+f"(c[3])
        : "r"(a0), "r"(a1), "r"(a2), "r"(a3), "r"(b0), "r"(b1));
}

// ================= split-bf16 tensor-core GEMM (mma.sync) =================
// C[m,n] = scale * sum_k A(m,k)*B(n,k) (+bias[m]) (optional GELU)
// OUT=0: fp32 to Cg.  OUT=1: bf16 hi/lo to CH/CL (row-major, coalesced via smem).
// OUT=2: bf16 hi/lo TRANSPOSED (CT[n, m]) to CH/CL (coalesced via smem).
#define KC 64
#define STG_BYTES 65536u       // Ah 16K | Al 16K | Bh 16K | Bl 16K
#define NSTG 3
#define TG_SMEM (3*65536 + 1024)

__device__ __forceinline__ void load_tiles(
    uint32_t sb,
    const __nv_bfloat16* pAh, const __nv_bfloat16* pAl,
    const __nv_bfloat16* pBh, const __nv_bfloat16* pBl,
    int m0, int n0, int k0, int lda, int ldb, int tid)
{
    #pragma unroll
    for (int it = 0; it < 4; it++) {
        const int slot = tid + it*256;          // 0..1023 : 128 rows x 8 chunks
        const int r = slot >> 3, c = slot & 7;
        const uint32_t sw = (uint32_t)(r*128) + (uint32_t)((c ^ (r & 7)) * 16);
        const long long ga = (long long)(m0 + r)*lda + k0 + c*8;
        const long long gb = (long long)(n0 + r)*ldb + k0 + c*8;
        cpa16(sb +     0 + sw, pAh + ga);
        cpa16(sb + 16384 + sw, pAl + ga);
        cpa16(sb + 32768 + sw, pBh + gb);
        cpa16(sb + 49152 + sw, pBl + gb);
    }
}

template<int DOGELU, int HASBIAS, int OUT>
__global__ __launch_bounds__(256, 1) void tgemm_k(
    const __nv_bfloat16* __restrict__ Agh, const __nv_bfloat16* __restrict__ Agl,
    const __nv_bfloat16* __restrict__ Bgh, const __nv_bfloat16* __restrict__ Bgl,
    float* __restrict__ Cg, const float* __restrict__ biasg,
    __nv_bfloat16* __restrict__ CH, __nv_bfloat16* __restrict__ CL,
    int K, int lda, int ldb, int ldc, int heads, int aMod,
    long long aSB, long long aSH, long long bSB, long long bSH,
    long long cSB, long long cSH, long long biasSB, float scale)
{
    extern __shared__ char dsm[];
    char* ap = (char*)(((uintptr_t)dsm + 1023) & ~(uintptr_t)1023);
    const uint32_t base = s2u(ap);
    const int tid = threadIdx.x;
    const int lane = tid & 31;
    const int wid = tid >> 5;
    const int wm = wid >> 2, wn = wid & 3;      // 2 x 4 warp grid, warp tile 64x32

    const int z = blockIdx.z, bb = z / heads, hh = z % heads;
    const __nv_bfloat16* pAh = Agh + (long long)(bb % aMod)*aSB + (long long)hh*aSH;
    const __nv_bfloat16* pAl = Agl + (long long)(bb % aMod)*aSB + (long long)hh*aSH;
    const __nv_bfloat16* pBh = Bgh + (long long)bb*bSB + (long long)hh*bSH;
    const __nv_bfloat16* pBl = Bgl + (long long)bb*bSB + (long long)hh*bSH;
    const long long cOff = (long long)bb*cSB + (long long)hh*cSH;
    const int m0 = blockIdx.y * 128;
    const int n0 = blockIdx.x * 128;

    float acc[4][4][4];
    #pragma unroll
    for (int i = 0; i < 4; i++)
        #pragma unroll
        for (int j = 0; j < 4; j++)
            #pragma unroll
            for (int r = 0; r < 4; r++) acc[i][j][r] = 0.f;

    const int NC = K / KC;
    const int NP = NC < NSTG ? NC : NSTG;
    for (int p = 0; p < NP; p++) {
        load_tiles(base + (uint32_t)p*STG_BYTES, pAh, pAl, pBh, pBl, m0, n0, p*KC, lda, ldb, tid);
        cpa_commit();
    }

    #pragma unroll 1
    for (int c = 0; c < NC; c++) {
        const uint32_t sb = base + (uint32_t)(c % NSTG) * STG_BYTES;
        const int rem = NC - 1 - c;
        if (rem >= 2) cpa_wait<2>(); else if (rem == 1) cpa_wait<1>(); else cpa_wait<0>();
        __syncthreads();

        #pragma unroll
        for (int kk = 0; kk < 4; kk++) {        // 4 k16 steps per 64-chunk
            const int colc = kk*2 + (lane >> 4);
            uint32_t ah[4][4], al[4][4];
            #pragma unroll
            for (int mt = 0; mt < 4; mt++) {
                const int r = wm*64 + mt*16 + (lane & 15);
                const uint32_t ad = sb + (uint32_t)(r*128) + (uint32_t)((colc ^ (r & 7)) * 16);
                ldm4(ah[mt][0], ah[mt][1], ah[mt][2], ah[mt][3], ad);
                ldm4(al[mt][0], al[mt][1], al[mt][2], al[mt][3], ad + 16384);
            }
            uint32_t bh[2][4], bl[2][4];
            #pragma unroll
            for (int nt = 0; nt < 2; nt++) {
                const int r = wn*32 + nt*16 + (lane & 15);
                const uint32_t bd = sb + 32768 + (uint32_t)(r*128) + (uint32_t)((colc ^ (r & 7)) * 16);
                ldm4(bh[nt][0], bh[nt][1], bh[nt][2], bh[nt][3], bd);
                ldm4(bl[nt][0], bl[nt][1], bl[nt][2], bl[nt][3], bd + 16384);
            }
            #pragma unroll
            for (int mt = 0; mt < 4; mt++) {
                #pragma unroll
                for (int n8 = 0; n8 < 4; n8++) {
                    const int nt = n8 >> 1, j = n8 & 1;
                    float* cc = acc[mt][n8];
                    mma16816(cc, ah[mt][0], ah[mt][1], ah[mt][2], ah[mt][3], bh[nt][j], bh[nt][j+2]);
                    mma16816(cc, ah[mt][0], ah[mt][1], ah[mt][2], ah[mt][3], bl[nt][j], bl[nt][j+2]);
                    mma16816(cc, al[mt][0], al[mt][1], al[mt][2], al[mt][3], bh[nt][j], bh[nt][j+2]);
                }
            }
        }
        __syncthreads();
        if (c + NSTG < NC) {
            load_tiles(base + (uint32_t)(c % NSTG) * STG_BYTES, pAh, pAl, pBh, pBl,
                       m0, n0, (c + NSTG) * KC, lda, ldb, tid);
            cpa_commit();
        }
    }

    const float* bp = HASBIAS ? (biasg + (long long)(bb % aMod)*biasSB) : nullptr;

    if (OUT == 1 || OUT == 2) {
        // stage tile in smem with coalesced-write layout, then row-contiguous stores
        __syncthreads();
        float* tb = (float*)ap;                 // OUT==1: [m][n] pad 132 ; OUT==2: [n][m] pad 132
        #pragma unroll
        for (int mt = 0; mt < 4; mt++) {
            const int r0l = wm*64 + mt*16 + (lane >> 2);
            const int r1l = r0l + 8;
            const float bv0 = HASBIAS ? bp[m0 + r0l] : 0.f;
            const float bv1 = HASBIAS ? bp[m0 + r1l] : 0.f;
            #pragma unroll
            for (int n8 = 0; n8 < 4; n8++) {
                const int cn = wn*32 + n8*8 + (lane & 3)*2;
                float v0 = acc[mt][n8][0]*scale + bv0;
                float v1 = acc[mt][n8][1]*scale + bv0;
                float v2 = acc[mt][n8][2]*scale + bv1;
                float v3 = acc[mt][n8][3]*scale + bv1;
                if (DOGELU) { v0 = gelu_f(v0); v1 = gelu_f(v1); v2 = gelu_f(v2); v3 = gelu_f(v3); }
                if (OUT == 2) {
                    tb[(cn  )*132 + r0l] = v0;
                    tb[(cn+1)*132 + r0l] = v1;
                    tb[(cn  )*132 + r1l] = v2;
                    tb[(cn+1)*132 + r1l] = v3;
                } else {
                    tb[r0l*132 + cn] = v0; tb[r0l*132 + cn + 1] = v1;
                    tb[r1l*132 + cn] = v2; tb[r1l*132 + cn + 1] = v3;
                }
            }
        }
        __syncthreads();
        #pragma unroll 1
        for (int r = wid; r < 128; r += 8) {
            const float4 v = *(const float4*)(tb + r*132 + lane*4);
            __nv_bfloat16 hb[4], lb[4];
            split2(v.x, hb[0], lb[0]); split2(v.y, hb[1], lb[1]);
            split2(v.z, hb[2], lb[2]); split2(v.w, hb[3], lb[3]);
            long long o;
            if (OUT == 2) o = cOff + (long long)(n0 + r)*ldc + m0 + lane*4;
            else          o = cOff + (long long)(m0 + r)*ldc + n0 + lane*4;
            *(uint2*)(CH + o) = *(uint2*)hb;
            *(uint2*)(CL + o) = *(uint2*)lb;
        }
        return;
    }

    #pragma unroll
    for (int mt = 0; mt < 4; mt++) {
        const int r0 = m0 + wm*64 + mt*16 + (lane >> 2);
        const int r1 = r0 + 8;
        const float bv0 = HASBIAS ? bp[r0] : 0.f;
        const float bv1 = HASBIAS ? bp[r1] : 0.f;
        #pragma unroll
        for (int n8 = 0; n8 < 4; n8++) {
            const int cn = n0 + wn*32 + n8*8 + (lane & 3)*2;
            float v0 = acc[mt][n8][0]*scale + bv0;
            float v1 = acc[mt][n8][1]*scale + bv0;
            float v2 = acc[mt][n8][2]*scale + bv1;
            float v3 = acc[mt][n8][3]*scale + bv1;
            if (DOGELU) { v0 = gelu_f(v0); v1 = gelu_f(v1); v2 = gelu_f(v2); v3 = gelu_f(v3); }
            *(float2*)&Cg[cOff + (long long)r0*ldc + cn] = make_float2(v0, v1);
            *(float2*)&Cg[cOff + (long long)r1*ldc + cn] = make_float2(v2, v3);
        }
    }
}

// ================= fp32 -> bf16 hi/lo splits =================
__global__ __launch_bounds__(256) void split_k(
    const float* __restrict__ x, __nv_bfloat16* __restrict__ oh,
    __nv_bfloat16* __restrict__ ol, int n4)
{
    const int i = blockIdx.x * 256 + threadIdx.x;
    if (i >= n4) return;
    const float4 v = ((const float4*)x)[i];
    __nv_bfloat162 h0, h1, l0, l1;
    split2(v.x, h0.x, l0.x); split2(v.y, h0.y, l0.y);
    split2(v.z, h1.x, l1.x); split2(v.w, h1.y, l1.y);
    ((__nv_bfloat162*)oh)[i*2]   = h0; ((__nv_bfloat162*)oh)[i*2+1] = h1;
    ((__nv_bfloat162*)ol)[i*2]   = l0; ((__nv_bfloat162*)ol)[i*2+1] = l1;
}

// transpose+split: in [bc, R, W] fp32 -> out [bc, W, R] bf16 hi/lo
__global__ __launch_bounds__(256) void splitT_k(
    const float* __restrict__ x, __nv_bfloat16* __restrict__ oh,
    __nv_bfloat16* __restrict__ ol, int R)
{
    __shared__ float t[32][33];
    const int bc = blockIdx.z;
    const int w0 = blockIdx.x * 32, r0 = blockIdx.y * 32;
    const int tx = threadIdx.x, ty = threadIdx.y;     // (32,8)
    const float* xb = x + (size_t)bc * R * Ww;
    #pragma unroll
    for (int i = 0; i < 4; i++)
        t[ty + i*8][tx] = xb[(size_t)(r0 + ty + i*8) * Ww + w0 + tx];
    __syncthreads();
    __nv_bfloat16* ohb = oh + (size_t)bc * Ww * R;
    __nv_bfloat16* olb = ol + (size_t)bc * Ww * R;
    #pragma unroll
    for (int i = 0; i < 4; i++) {
        const float v = t[tx][ty + i*8];
        __nv_bfloat16 h, l; split2(v, h, l);
        const size_t o = (size_t)(w0 + ty + i*8) * R + r0 + tx;
        ohb[o] = h; olb[o] = l;
    }
}

// ---------------- fused conv1x7 + RoPE + transpose-split (Q/K path) ----------------
__global__ __launch_bounds__(256) void convrope_k(
    const float* __restrict__ x, __nv_bfloat16* __restrict__ oh,
    __nv_bfloat16* __restrict__ ol,
    const float* __restrict__ wt, const float* __restrict__ bs)
{
    __shared__ float xin[2][32][40];
    __shared__ float cv[2][32][33];
    const int b = blockIdx.z;
    const int w0 = blockIdx.x*32, f0 = blockIdx.y*32;
    const int tx = threadIdx.x, ty = threadIdx.y;
    const int tid = ty*32 + tx;

    for (int i = tid; i < 2*32*38; i += 256) {
        const int ci = i / (32*38), rem = i % (32*38);
        const int fi = rem / 38, wi = rem % 38;
        const int wg = w0 + wi - 3;
        xin[ci][fi][wi] = ((unsigned)wg < (unsigned)Ww)
            ? x[((size_t)(b*2 + ci)*Ff + f0 + fi)*Ww + wg] : 0.f;
    }
    __syncthreads();

    float wreg[2][2][7];
    #pragma unroll
    for (int co = 0; co < 2; co++)
        #pragma unroll
        for (int ci = 0; ci < 2; ci++)
            #pragma unroll
            for (int j = 0; j < 7; j++)
                wreg[co][ci][j] = wt[(co*2 + ci)*7 + j];
    const float b0 = bs[0], b1 = bs[1];

    #pragma unroll
    for (int r = 0; r < 4; r++) {
        const int fi = ty*4 + r;
        float a0 = b0, a1 = b1;
        #pragma unroll
        for (int ci = 0; ci < 2; ci++)
            #pragma unroll
            for (int j = 0; j < 7; j++) {
                const float xv = xin[ci][fi][tx + j];
                a0 = fmaf(xv, wreg[0][ci][j], a0);
                a1 = fmaf(xv, wreg[1][ci][j], a1);
            }
        cv[0][fi][tx] = a0; cv[1][fi][tx] = a1;
    }
    __syncthreads();

    const int co = tid >> 7, wl = (tid >> 2) & 31, fq = (tid & 3) * 8;
    const int wg = w0 + wl;
    uint4 hv, lv;
    __nv_bfloat16* hb = (__nv_bfloat16*)&hv;
    __nv_bfloat16* lb = (__nv_bfloat16*)&lv;
    #pragma unroll
    for (int p = 0; p < 4; p++) {
        const int fl = fq + p*2;
        const float x0 = cv[co][fl][wl], x1 = cv[co][fl + 1][wl];
        const int fg = f0 + fl;
        const int ttp = (fg >> 1) & 127;
        const float inv = expf(-(float)ttp * (9.2103403719761836f / 128.f));
        float sn, cn; sincosf((float)wg * inv, &sn, &cn);
        const float y0 = x0*cn - x1*sn;
        const float y1 = x1*cn + x0*sn;
        split2(y0, hb[p*2],   lb[p*2]);
        split2(y1, hb[p*2+1], lb[p*2+1]);
    }
    const size_t o = ((size_t)(b*2 + co)*Ww + wg)*Ff + f0 + fq;
    *(uint4*)(oh + o) = hv;
    *(uint4*)(ol + o) = lv;
}

// ---------------- fused conv1x7 + split (V path), layout preserved ----------------
__global__ __launch_bounds__(256) void convsplit_k(
    const float* __restrict__ x, __nv_bfloat16* __restrict__ oh,
    __nv_bfloat16* __restrict__ ol,
    const float* __restrict__ wt, const float* __restrict__ bs)
{
    const int t = blockIdx.x * 256 + threadIdx.x;
    const int wc = t & 1023;
    const int f  = (t >> 10) & 1023;
    const int co = (t >> 20) & 1;
    const int bb = t >> 21;
    float s = bs[co];
    #pragma unroll
    for (int ci = 0; ci < Cc; ci++) {
        const float* row = x + ((size_t)(bb*Cc + ci) * Ff + f) * Ww;
        const float* wp  = wt + (co*Cc + ci) * 7;
        #pragma unroll
        for (int j = 0; j < 7; j++) {
            const int ww = wc + j - 3;
            if ((unsigned)ww < (unsigned)Ww) s = fmaf(row[ww], wp[j], s);
        }
    }
    __nv_bfloat16 h, l; split2(s, h, l);
    oh[t] = h; ol[t] = l;
}

// ---------------- conv 3x3 (pad 1), optional GELU ----------------
__global__ __launch_bounds__(256) void conv3x3_k(
    const float* __restrict__ x, float* __restrict__ y,
    const float* __restrict__ wt, const float* __restrict__ bs, int dogelu)
{
    const int t = blockIdx.x * 256 + threadIdx.x;
    const int wc = t & 1023;
    const int f  = (t >> 10) & 1023;
    const int co = (t >> 20) & 1;
    const int bb = t >> 21;
    float s = bs[co];
    #pragma unroll
    for (int ci = 0; ci < Cc; ci++) {
        const float* xp = x + ((size_t)(bb*Cc + ci)) * FW;
        const float* wp = wt + (co*Cc + ci) * 9;
        #pragma unroll
        for (int ky = 0; ky < 3; ky++) {
            const int ff = f + ky - 1;
            if ((unsigned)ff < (unsigned)Ff) {
                const float* row = xp + (size_t)ff * Ww;
                #pragma unroll
                for (int kx = 0; kx < 3; kx++) {
                    const int ww = wc + kx - 1;
                    if ((unsigned)ww < (unsigned)Ww) s = fmaf(row[ww], wp[ky*3+kx], s);
                }
            }
        }
    }
    if (dogelu) s = gelu_f(s);
    y[t] = s;
}

// ---------------- row softmax -> bf16 hi/lo ----------------
__global__ __launch_bounds__(256) void softmax_k(
    const float* __restrict__ sp, __nv_bfloat16* __restrict__ oh,
    __nv_bfloat16* __restrict__ ol)
{
    const size_t row = blockIdx.x;
    const float* p = sp + row * Ww;
    const int t = threadIdx.x, lane = t & 31, wid = t >> 5;
    float4 v = ((const float4*)p)[t];
    float mx = fmaxf(fmaxf(v.x, v.y), fmaxf(v.z, v.w));
    #pragma unroll
    for (int o = 16; o > 0; o >>= 1) mx = fmaxf(mx, __shfl_xor_sync(0xffffffffu, mx, o));
    __shared__ float red[8];
    if (lane == 0) red[wid] = mx;
    __syncthreads();
    mx = red[0];
    #pragma unroll
    for (int i = 1; i < 8; i++) mx = fmaxf(mx, red[i]);
    __syncthreads();
    v.x = expf(v.x - mx); v.y = expf(v.y - mx); v.z = expf(v.z - mx); v.w = expf(v.w - mx);
    float sm = v.x + v.y + v.z + v.w;
    #pragma unroll
    for (int o = 16; o > 0; o >>= 1) sm += __shfl_xor_sync(0xffffffffu, sm, o);
    if (lane == 0) red[wid] = sm;
    __syncthreads();
    sm = red[0]+red[1]+red[2]+red[3]+red[4]+red[5]+red[6]+red[7];
    const float r = 1.f / sm;
    v.x *= r; v.y *= r; v.z *= r; v.w *= r;
    __nv_bfloat162 h0, h1, l0, l1;
    split2(v.x, h0.x, l0.x); split2(v.y, h0.y, l0.y);
    split2(v.z, h1.x, l1.x); split2(v.w, h1.y, l1.y);
    ((__nv_bfloat162*)(oh + row*Ww))[t*2]   = h0;
    ((__nv_bfloat162*)(oh + row*Ww))[t*2+1] = h1;
    ((__nv_bfloat162*)(ol + row*Ww))[t*2]   = l0;
    ((__nv_bfloat162*)(ol + row*Ww))[t*2+1] = l1;
}

// ---------------- residual + LayerNorm over F, h <- LN(h+z), smem value cache ----------------
__global__ __launch_bounds__(512) void lnres_k(
    float* __restrict__ h, const float* __restrict__ z,
    const float* __restrict__ g, const float* __restrict__ b)
{
    extern __shared__ float val[];                  // [1024][32]
    const int tx = threadIdx.x, ty = threadIdx.y;
    const int wc = blockIdx.x * 32 + tx;
    const int bc = blockIdx.y;
    const int c  = bc & 1;
    float* hp = h + (size_t)bc * FW + wc;
    const float* zp = z + (size_t)bc * FW + wc;
    float sum = 0.f, sq = 0.f;
    for (int f = ty; f < Ff; f += 16) {
        const float v = hp[(size_t)f * Ww] + zp[(size_t)f * Ww];
        val[f*32 + tx] = v;
        sum += v; sq += v * v;
    }
    __shared__ float s1[16][32], s2[16][32];
    __shared__ float smu[32], srs[32];
    s1[ty][tx] = sum; s2[ty][tx] = sq;
    __syncthreads();
    if (ty == 0) {
        float a = 0.f, q = 0.f;
        #pragma unroll
        for (int r = 0; r < 16; r++) { a += s1[r][tx]; q += s2[r][tx]; }
        const float mu = a * (1.f / Ff);
        const float var = q * (1.f / Ff) - mu * mu;
        smu[tx] = mu; srs[tx] = rsqrtf(var + 1e-5f);
    }
    __syncthreads();
    const float mu = smu[tx], rs = srs[tx];
    for (int f = ty; f < Ff; f += 16) {
        const float v = val[f*32 + tx];
        hp[(size_t)f * Ww] = (v - mu) * rs * g[c*Ff + f] + b[c*Ff + f];
    }
}

// ---------------- 2-channel mix (1x1 conv / output projection) ----------------
__global__ __launch_bounds__(256) void chanmix_k(
    const float* __restrict__ in, float* __restrict__ out,
    const float* __restrict__ m, const float* __restrict__ bs)
{
    const int t = blockIdx.x * 256 + threadIdx.x;
    const int pos = t & (FW - 1);
    const int co  = (t >> 20) & 1;
    const int bb  = t >> 21;
    float s = bs ? bs[co] : 0.f;
    s = fmaf(in[(size_t)(bb*Cc + 0) * FW + pos], m[co*Cc + 0], s);
    s = fmaf(in[(size_t)(bb*Cc + 1) * FW + pos], m[co*Cc + 1], s);
    out[t] = s;
}

// ---------------- launch ----------------
extern "C" void kernel_launch(void* const* d_in, const int* in_sizes, int n_in,
                              void* d_out, int out_size)
{
    (void)in_sizes; (void)n_in; (void)out_size;
    const float* x       = (const float*)d_in[0];
    const float* enc_c1w = (const float*)d_in[1];
    const float* enc_c1b = (const float*)d_in[2];
    const float* enc_c2w = (const float*)d_in[3];
    const float* enc_c2b = (const float*)d_in[4];
    const float* enc_nw  = (const float*)d_in[5];
    const float* enc_nb  = (const float*)d_in[6];
    const float* qw  = (const float*)d_in[7];
    const float* qb  = (const float*)d_in[8];
    const float* qcw = (const float*)d_in[9];
    const float* qcb = (const float*)d_in[10];
    const float* kw  = (const float*)d_in[11];
    const float* kb  = (const float*)d_in[12];
    const float* kcw = (const float*)d_in[13];
    const float* kcb = (const float*)d_in[14];
    const float* vw  = (const float*)d_in[15];
    const float* vb  = (const float*)d_in[16];
    const float* vcw = (const float*)d_in[17];
    const float* vcb = (const float*)d_in[18];
    const float* ow  = (const float*)d_in[19];
    const float* ob  = (const float*)d_in[20];
    const float* ocw = (const float*)d_in[21];
    const float* ocb = (const float*)d_in[22];
    const float* n1w = (const float*)d_in[23];
    const float* n1b = (const float*)d_in[24];
    const float* f1w = (const float*)d_in[25];
    const float* f1b = (const float*)d_in[26];
    const float* f2w = (const float*)d_in[27];
    const float* f2b = (const float*)d_in[28];
    const float* n2w = (const float*)d_in[29];
    const float* n2b = (const float*)d_in[30];
    const float* out_w = (const float*)d_in[31];

    float *h, *t0, *t1, *s;
    __nv_bfloat16 *hTh,*hTl,*qTh,*qTl,*kTh,*kTl,*vh,*vl,*sh,*sl,*uTh,*uTl,*wh,*wl;
    cudaGetSymbolAddress((void**)&h,  g_h);
    cudaGetSymbolAddress((void**)&t0, g_t0);
    cudaGetSymbolAddress((void**)&t1, g_t1);
    cudaGetSymbolAddress((void**)&s,  g_s);
    cudaGetSymbolAddress((void**)&hTh, g_hTh); cudaGetSymbolAddress((void**)&hTl, g_hTl);
    cudaGetSymbolAddress((void**)&qTh, g_qTh); cudaGetSymbolAddress((void**)&qTl, g_qTl);
    cudaGetSymbolAddress((void**)&kTh, g_kTh); cudaGetSymbolAddress((void**)&kTl, g_kTl);
    cudaGetSymbolAddress((void**)&vh,  g_vh);  cudaGetSymbolAddress((void**)&vl,  g_vl);
    cudaGetSymbolAddress((void**)&sh,  g_sh);  cudaGetSymbolAddress((void**)&sl,  g_sl);
    cudaGetSymbolAddress((void**)&uTh, g_uTh); cudaGetSymbolAddress((void**)&uTl, g_uTl);
    cudaGetSymbolAddress((void**)&wh,  g_wh);  cudaGetSymbolAddress((void**)&wl,  g_wl);

    cudaFuncSetAttribute(tgemm_k<0,1,0>, cudaFuncAttributeMaxDynamicSharedMemorySize, TG_SMEM);
    cudaFuncSetAttribute(tgemm_k<0,0,0>, cudaFuncAttributeMaxDynamicSharedMemorySize, TG_SMEM);
    cudaFuncSetAttribute(tgemm_k<0,0,1>, cudaFuncAttributeMaxDynamicSharedMemorySize, TG_SMEM);
    cudaFuncSetAttribute(tgemm_k<1,1,2>, cudaFuncAttributeMaxDynamicSharedMemorySize, TG_SMEM);
    cudaFuncSetAttribute(lnres_k, cudaFuncAttributeMaxDynamicSharedMemorySize, 131072);

    const int EW = 16384;
    const dim3 LN_G(Ww/32, BC), LN_B(32, 16);
    const int BIG = 1 << 24;
    const dim3 CR_G(Ww/32, Ff/32, Bn), CR_B(32, 8);
    const dim3 ST_B(32, 8);
    const dim3 ST_F(Ww/32, Ff/32, BC);

    cudaMemcpyAsync(h, x, sizeof(float) * (size_t)BC * FW, cudaMemcpyDeviceToDevice, 0);

    // weight-style linear (fp32 out): C[bc, M, W] = W[c, M, K] @ XT[bc, W, K]^T + bias
    auto WG = [&](const __nv_bfloat16* Ah, const __nv_bfloat16* Al,
                  const __nv_bfloat16* Bh, const __nv_bfloat16* Bl,
                  float* Cx, const float* bias, int M, int K, long long cRow) {
        dim3 grid(Ww/128, M/128, BC);
        tgemm_k<0,1,0><<<grid,256,TG_SMEM>>>(Ah, Al, Bh, Bl, Cx, bias, nullptr, nullptr,
            K, K, K, Ww, 1, Cc, (long long)M*K, 0, (long long)Ww*K, 0,
            cRow, 0, (long long)M, 1.f);
    };

    // --------- FrameEncoder: 3 ResBlocks ---------
    for (int nb = 0; nb < NBn; nb++) {
        conv3x3_k<<<EW,256>>>(h,  t0, enc_c1w + nb*Cc*Cc*9, enc_c1b + nb*Cc, 1);
        conv3x3_k<<<EW,256>>>(t0, t1, enc_c2w + nb*Cc*Cc*9, enc_c2b + nb*Cc, 0);
        lnres_k<<<LN_G,LN_B,131072>>>(h, t1, enc_nw + nb*Cc*Ff, enc_nb + nb*Cc*Ff);
    }

    // --------- Transformer layers ---------
    for (int l = 0; l < Ll; l++) {
        const long long lwF = (long long)l * Cc * Ff * Ff;
        const long long lwE = (long long)l * Cc * EF * Ff;

        splitT_k<<<ST_F,ST_B>>>(h, hTh, hTl, Ff);   // [bc,W,F]

        // Q: linear -> fused conv1x7+rope+transpose-split
        split_k<<<2048,256>>>(qw + lwF, wh, wl, Cc*Ff*Ff/4);
        WG(wh, wl, hTh, hTl, t0, qb + l*Cc*Ff, Ff, Ff, (long long)FW);
        convrope_k<<<CR_G,CR_B>>>(t0, qTh, qTl, qcw + l*Cc*Cc*7, qcb + l*Cc);
        // K
        split_k<<<2048,256>>>(kw + lwF, wh, wl, Cc*Ff*Ff/4);
        WG(wh, wl, hTh, hTl, t0, kb + l*Cc*Ff, Ff, Ff, (long long)FW);
        convrope_k<<<CR_G,CR_B>>>(t0, kTh, kTl, kcw + l*Cc*Cc*7, kcb + l*Cc);
        // V: linear -> fused conv1x7+split (layout [F,W])
        split_k<<<2048,256>>>(vw + lwF, wh, wl, Cc*Ff*Ff/4);
        WG(wh, wl, hTh, hTl, t0, vb + l*Cc*Ff, Ff, Ff, (long long)FW);
        convsplit_k<<<EW,256>>>(t0, vh, vl, vcw + l*Cc*Cc*7, vcb + l*Cc);

        // scores[z=bc*4+h, q, k] = Q[q,:] . K[k,:] / 32
        tgemm_k<0,0,0><<<dim3(Ww/128, Ww/128, 16),256,TG_SMEM>>>(
            qTh, qTl, kTh, kTl, s, nullptr, nullptr, nullptr,
            Dd, Ff, Ff, Ww, Hh, BIG,
            (long long)FW, (long long)Dd, (long long)FW, (long long)Dd,
            4LL*WW, (long long)WW, 0, 0.03125f);
        softmax_k<<<16*1024,256>>>(s, sh, sl);
        // attnT[bc, q, h*256+d] -> bf16 split directly (reuse qT buffers)
        tgemm_k<0,0,1><<<dim3(Dd/128, Ww/128, 16),256,TG_SMEM>>>(
            sh, sl, vh, vl, nullptr, nullptr, qTh, qTl,
            Ww, Ww, Ww, Ff, Hh, BIG,
            4LL*WW, (long long)WW, (long long)FW, (long long)Dd*Ww,
            (long long)FW, (long long)Dd, 0, 1.f);

        // output projection + 1x1 channel conv + residual LN
        split_k<<<2048,256>>>(ow + lwF, wh, wl, Cc*Ff*Ff/4);
        WG(wh, wl, qTh, qTl, t1, ob + l*Cc*Ff, Ff, Ff, (long long)FW);
        chanmix_k<<<EW,256>>>(t1, t0, ocw + l*Cc*Cc, ocb + l*Cc);
        lnres_k<<<LN_G,LN_B,131072>>>(h, t0, n1w + l*Cc*Ff, n1b + l*Cc*Ff);

        // FFN: f1 writes transposed bf16 split directly (OUT=2, GELU)
        splitT_k<<<ST_F,ST_B>>>(h, hTh, hTl, Ff);
        split_k<<<8192,256>>>(f1w + lwE, wh, wl, Cc*EF*Ff/4);
        tgemm_k<1,1,2><<<dim3(Ww/128, EF/128, BC),256,TG_SMEM>>>(
            wh, wl, hTh, hTl, nullptr, f1b + l*Cc*EF, uTh, uTl,
            Ff, Ff, Ff, EF, 1, Cc,
            (long long)EF*Ff, 0, (long long)Ww*Ff, 0,
            (long long)Ww*EF, 0, (long long)EF, 1.f);
        split_k<<<8192,256>>>(f2w + lwE, wh, wl, Cc*Ff*EF/4);
        WG(wh, wl, uTh, uTl, t0, f2b + l*Cc*Ff, Ff, EF, (long long)FW);
        lnres_k<<<LN_G,LN_B,131072>>>(h, t0, n2w + l*Cc*Ff, n2b + l*Cc*Ff);
    }

    // --------- output channel mix ---------
    chanmix_k<<<EW,256>>>(h, (float*)d_out, out_w, nullptr);
}

// round 10
// speedup vs baseline: 1.0462x; 1.0048x over previous
#include <cuda_runtime.h>
#include <cuda_bf16.h>
#include <math.h>
#include <cstdint>

// Problem constants
#define Bn 2
#define Cc 2
#define Ff 1024
#define Ww 1024
#define Hh 4
#define Dd 256
#define EF 4096
#define Ll 15
#define NBn 3
#define BC 4              // B*C
#define FW (Ff*Ww)        // 1048576
#define WW (Ww*Ww)        // 1048576

// ---------------- scratch (device globals; no allocations) ----------------
__device__ float g_h [BC*FW];
__device__ float g_t0[BC*FW];
__device__ float g_t1[BC*FW];
__device__ float g_s [16*WW];                 // attention scores fp32 [bc,h,Wq,Wk]

__device__ __nv_bfloat16 g_hTh[BC*FW], g_hTl[BC*FW];   // [bc,W,F] transposed activations
__device__ __nv_bfloat16 g_qTh[BC*FW], g_qTl[BC*FW];   // [bc,W,F] (reused for attnT)
__device__ __nv_bfloat16 g_kTh[BC*FW], g_kTl[BC*FW];
__device__ __nv_bfloat16 g_vh [BC*FW], g_vl [BC*FW];   // V [bc,F,W]
__device__ __nv_bfloat16 g_sh [16*WW], g_sl [16*WW];   // softmax out bf16 split
__device__ __nv_bfloat16 g_uTh[(size_t)BC*Ww*EF], g_uTl[(size_t)BC*Ww*EF]; // [bc,W,EF]
__device__ __nv_bfloat16 g_wh [(size_t)Cc*EF*Ff], g_wl[(size_t)Cc*EF*Ff];  // weight split scratch

__device__ __forceinline__ float gelu_f(float x) {
    return 0.5f * x * (1.0f + erff(x * 0.70710678118654752f));
}
__device__ __forceinline__ void split2(float v, __nv_bfloat16& h, __nv_bfloat16& l){
    h = __float2bfloat16(v);
    l = __float2bfloat16(v - __bfloat162float(h));
}

// ================= async-copy / mma.sync helpers =================
__device__ __forceinline__ uint32_t s2u(const void* p){
    uint32_t a;
    asm("{ .reg .u64 t; cvta.to.shared.u64 t, %1; cvt.u32.u64 %0, t; }" : "=r"(a) : "l"(p));
    return a;
}
__device__ __forceinline__ void cpa16(uint32_t dst, const void* src){
    asm volatile("cp.async.cg.shared.global [%0], [%1], 16;" :: "r"(dst), "l"(src));
}
__device__ __forceinline__ void cpa_commit(){ asm volatile("cp.async.commit_group;" ::: "memory"); }
template<int N> __device__ __forceinline__ void cpa_wait(){
    asm volatile("cp.async.wait_group %0;" :: "n"(N) : "memory");
}
__device__ __forceinline__ void ldm4(uint32_t& r0, uint32_t& r1, uint32_t& r2, uint32_t& r3, uint32_t a){
    asm volatile("ldmatrix.sync.aligned.m8n8.x4.shared.b16 {%0,%1,%2,%3}, [%4];"
                 : "=r"(r0), "=r"(r1), "=r"(r2), "=r"(r3) : "r"(a));
}
__device__ __forceinline__ void mma16816(float* c,
    uint32_t a0, uint32_t a1, uint32_t a2, uint32_t a3, uint32_t b0, uint32_t b1){
    asm volatile(
        "mma.sync.aligned.m16n8k16.row.col.f32.bf16.bf16.f32 "
        "{%0,%1,%2,%3}, {%4,%5,%6,%7}, {%8,%9}, {%0,%1,%2,%3};"
        : "+f"(c[0]), "+f"(c[1]), "+f"(c[2]), "+f"(c[3])
        : "r"(a0), "r"(a1), "r"(a2), "r"(a3), "r"(b0), "r"(b1));
}

// ================= split-bf16 tensor-core GEMM (mma.sync) =================
// C[m,n] = scale * sum_k A(m,k)*B(n,k) (+bias[m]) (optional GELU)
// OUT=0: fp32 to Cg.  OUT=1: bf16 hi/lo to CH/CL (row-major, coalesced via smem).
// OUT=2: bf16 hi/lo TRANSPOSED (CT[n, m]) to CH/CL (coalesced via smem).
#define KC 64
#define STG_BYTES 65536u       // Ah 16K | Al 16K | Bh 16K | Bl 16K
#define NSTG 3
#define TG_SMEM (3*65536 + 1024)

__device__ __forceinline__ void load_tiles(
    uint32_t sb,
    const __nv_bfloat16* pAh, const __nv_bfloat16* pAl,
    const __nv_bfloat16* pBh, const __nv_bfloat16* pBl,
    int m0, int n0, int k0, int lda, int ldb, int tid)
{
    #pragma unroll
    for (int it = 0; it < 4; it++) {
        const int slot = tid + it*256;          // 0..1023 : 128 rows x 8 chunks
        const int r = slot >> 3, c = slot & 7;
        const uint32_t sw = (uint32_t)(r*128) + (uint32_t)((c ^ (r & 7)) * 16);
        const long long ga = (long long)(m0 + r)*lda + k0 + c*8;
        const long long gb = (long long)(n0 + r)*ldb + k0 + c*8;
        cpa16(sb +     0 + sw, pAh + ga);
        cpa16(sb + 16384 + sw, pAl + ga);
        cpa16(sb + 32768 + sw, pBh + gb);
        cpa16(sb + 49152 + sw, pBl + gb);
    }
}

template<int DOGELU, int HASBIAS, int OUT>
__global__ __launch_bounds__(256, 1) void tgemm_k(
    const __nv_bfloat16* __restrict__ Agh, const __nv_bfloat16* __restrict__ Agl,
    const __nv_bfloat16* __restrict__ Bgh, const __nv_bfloat16* __restrict__ Bgl,
    float* __restrict__ Cg, const float* __restrict__ biasg,
    __nv_bfloat16* __restrict__ CH, __nv_bfloat16* __restrict__ CL,
    int K, int lda, int ldb, int ldc, int heads, int aMod,
    long long aSB, long long aSH, long long bSB, long long bSH,
    long long cSB, long long cSH, long long biasSB, float scale)
{
    extern __shared__ char dsm[];
    char* ap = (char*)(((uintptr_t)dsm + 1023) & ~(uintptr_t)1023);
    const uint32_t base = s2u(ap);
    const int tid = threadIdx.x;
    const int lane = tid & 31;
    const int wid = tid >> 5;
    const int wm = wid >> 2, wn = wid & 3;      // 2 x 4 warp grid, warp tile 64x32

    const int z = blockIdx.z, bb = z / heads, hh = z % heads;
    const __nv_bfloat16* pAh = Agh + (long long)(bb % aMod)*aSB + (long long)hh*aSH;
    const __nv_bfloat16* pAl = Agl + (long long)(bb % aMod)*aSB + (long long)hh*aSH;
    const __nv_bfloat16* pBh = Bgh + (long long)bb*bSB + (long long)hh*bSH;
    const __nv_bfloat16* pBl = Bgl + (long long)bb*bSB + (long long)hh*bSH;
    const long long cOff = (long long)bb*cSB + (long long)hh*cSH;
    const int m0 = blockIdx.y * 128;
    const int n0 = blockIdx.x * 128;

    float acc[4][4][4];
    #pragma unroll
    for (int i = 0; i < 4; i++)
        #pragma unroll
        for (int j = 0; j < 4; j++)
            #pragma unroll
            for (int r = 0; r < 4; r++) acc[i][j][r] = 0.f;

    const int NC = K / KC;
    const int NP = NC < NSTG ? NC : NSTG;
    for (int p = 0; p < NP; p++) {
        load_tiles(base + (uint32_t)p*STG_BYTES, pAh, pAl, pBh, pBl, m0, n0, p*KC, lda, ldb, tid);
        cpa_commit();
    }

    #pragma unroll 1
    for (int c = 0; c < NC; c++) {
        const uint32_t sb = base + (uint32_t)(c % NSTG) * STG_BYTES;
        const int rem = NC - 1 - c;
        if (rem >= 2) cpa_wait<2>(); else if (rem == 1) cpa_wait<1>(); else cpa_wait<0>();
        __syncthreads();

        #pragma unroll
        for (int kk = 0; kk < 4; kk++) {        // 4 k16 steps per 64-chunk
            const int colc = kk*2 + (lane >> 4);
            uint32_t ah[4][4], al[4][4];
            #pragma unroll
            for (int mt = 0; mt < 4; mt++) {
                const int r = wm*64 + mt*16 + (lane & 15);
                const uint32_t ad = sb + (uint32_t)(r*128) + (uint32_t)((colc ^ (r & 7)) * 16);
                ldm4(ah[mt][0], ah[mt][1], ah[mt][2], ah[mt][3], ad);
                ldm4(al[mt][0], al[mt][1], al[mt][2], al[mt][3], ad + 16384);
            }
            uint32_t bh[2][4], bl[2][4];
            #pragma unroll
            for (int nt = 0; nt < 2; nt++) {
                const int r = wn*32 + nt*16 + (lane & 15);
                const uint32_t bd = sb + 32768 + (uint32_t)(r*128) + (uint32_t)((colc ^ (r & 7)) * 16);
                ldm4(bh[nt][0], bh[nt][1], bh[nt][2], bh[nt][3], bd);
                ldm4(bl[nt][0], bl[nt][1], bl[nt][2], bl[nt][3], bd + 16384);
            }
            #pragma unroll
            for (int mt = 0; mt < 4; mt++) {
                #pragma unroll
                for (int n8 = 0; n8 < 4; n8++) {
                    const int nt = n8 >> 1, j = n8 & 1;
                    float* cc = acc[mt][n8];
                    mma16816(cc, ah[mt][0], ah[mt][1], ah[mt][2], ah[mt][3], bh[nt][j], bh[nt][j+2]);
                    mma16816(cc, ah[mt][0], ah[mt][1], ah[mt][2], ah[mt][3], bl[nt][j], bl[nt][j+2]);
                    mma16816(cc, al[mt][0], al[mt][1], al[mt][2], al[mt][3], bh[nt][j], bh[nt][j+2]);
                }
            }
        }
        __syncthreads();
        if (c + NSTG < NC) {
            load_tiles(base + (uint32_t)(c % NSTG) * STG_BYTES, pAh, pAl, pBh, pBl,
                       m0, n0, (c + NSTG) * KC, lda, ldb, tid);
            cpa_commit();
        }
    }

    const float* bp = HASBIAS ? (biasg + (long long)(bb % aMod)*biasSB) : nullptr;

    if (OUT == 1 || OUT == 2) {
        // stage tile in smem with coalesced-write layout, then row-contiguous stores
        __syncthreads();
        float* tb = (float*)ap;                 // OUT==1: [m][n] pad 132 ; OUT==2: [n][m] pad 132
        #pragma unroll
        for (int mt = 0; mt < 4; mt++) {
            const int r0l = wm*64 + mt*16 + (lane >> 2);
            const int r1l = r0l + 8;
            const float bv0 = HASBIAS ? bp[m0 + r0l] : 0.f;
            const float bv1 = HASBIAS ? bp[m0 + r1l] : 0.f;
            #pragma unroll
            for (int n8 = 0; n8 < 4; n8++) {
                const int cn = wn*32 + n8*8 + (lane & 3)*2;
                float v0 = acc[mt][n8][0]*scale + bv0;
                float v1 = acc[mt][n8][1]*scale + bv0;
                float v2 = acc[mt][n8][2]*scale + bv1;
                float v3 = acc[mt][n8][3]*scale + bv1;
                if (DOGELU) { v0 = gelu_f(v0); v1 = gelu_f(v1); v2 = gelu_f(v2); v3 = gelu_f(v3); }
                if (OUT == 2) {
                    tb[(cn  )*132 + r0l] = v0;
                    tb[(cn+1)*132 + r0l] = v1;
                    tb[(cn  )*132 + r1l] = v2;
                    tb[(cn+1)*132 + r1l] = v3;
                } else {
                    tb[r0l*132 + cn] = v0; tb[r0l*132 + cn + 1] = v1;
                    tb[r1l*132 + cn] = v2; tb[r1l*132 + cn + 1] = v3;
                }
            }
        }
        __syncthreads();
        #pragma unroll 1
        for (int r = wid; r < 128; r += 8) {
            const float4 v = *(const float4*)(tb + r*132 + lane*4);
            __nv_bfloat16 hb[4], lb[4];
            split2(v.x, hb[0], lb[0]); split2(v.y, hb[1], lb[1]);
            split2(v.z, hb[2], lb[2]); split2(v.w, hb[3], lb[3]);
            long long o;
            if (OUT == 2) o = cOff + (long long)(n0 + r)*ldc + m0 + lane*4;
            else          o = cOff + (long long)(m0 + r)*ldc + n0 + lane*4;
            *(uint2*)(CH + o) = *(uint2*)hb;
            *(uint2*)(CL + o) = *(uint2*)lb;
        }
        return;
    }

    #pragma unroll
    for (int mt = 0; mt < 4; mt++) {
        const int r0 = m0 + wm*64 + mt*16 + (lane >> 2);
        const int r1 = r0 + 8;
        const float bv0 = HASBIAS ? bp[r0] : 0.f;
        const float bv1 = HASBIAS ? bp[r1] : 0.f;
        #pragma unroll
        for (int n8 = 0; n8 < 4; n8++) {
            const int cn = n0 + wn*32 + n8*8 + (lane & 3)*2;
            float v0 = acc[mt][n8][0]*scale + bv0;
            float v1 = acc[mt][n8][1]*scale + bv0;
            float v2 = acc[mt][n8][2]*scale + bv1;
            float v3 = acc[mt][n8][3]*scale + bv1;
            if (DOGELU) { v0 = gelu_f(v0); v1 = gelu_f(v1); v2 = gelu_f(v2); v3 = gelu_f(v3); }
            *(float2*)&Cg[cOff + (long long)r0*ldc + cn] = make_float2(v0, v1);
            *(float2*)&Cg[cOff + (long long)r1*ldc + cn] = make_float2(v2, v3);
        }
    }
}

// ================= fp32 -> bf16 hi/lo splits =================
__global__ __launch_bounds__(256) void split_k(
    const float* __restrict__ x, __nv_bfloat16* __restrict__ oh,
    __nv_bfloat16* __restrict__ ol, int n4)
{
    const int i = blockIdx.x * 256 + threadIdx.x;
    if (i >= n4) return;
    const float4 v = ((const float4*)x)[i];
    __nv_bfloat162 h0, h1, l0, l1;
    split2(v.x, h0.x, l0.x); split2(v.y, h0.y, l0.y);
    split2(v.z, h1.x, l1.x); split2(v.w, h1.y, l1.y);
    ((__nv_bfloat162*)oh)[i*2]   = h0; ((__nv_bfloat162*)oh)[i*2+1] = h1;
    ((__nv_bfloat162*)ol)[i*2]   = l0; ((__nv_bfloat162*)ol)[i*2+1] = l1;
}

// transpose+split: in [bc, R, W] fp32 -> out [bc, W, R] bf16 hi/lo
__global__ __launch_bounds__(256) void splitT_k(
    const float* __restrict__ x, __nv_bfloat16* __restrict__ oh,
    __nv_bfloat16* __restrict__ ol, int R)
{
    __shared__ float t[32][33];
    const int bc = blockIdx.z;
    const int w0 = blockIdx.x * 32, r0 = blockIdx.y * 32;
    const int tx = threadIdx.x, ty = threadIdx.y;     // (32,8)
    const float* xb = x + (size_t)bc * R * Ww;
    #pragma unroll
    for (int i = 0; i < 4; i++)
        t[ty + i*8][tx] = xb[(size_t)(r0 + ty + i*8) * Ww + w0 + tx];
    __syncthreads();
    __nv_bfloat16* ohb = oh + (size_t)bc * Ww * R;
    __nv_bfloat16* olb = ol + (size_t)bc * Ww * R;
    #pragma unroll
    for (int i = 0; i < 4; i++) {
        const float v = t[tx][ty + i*8];
        __nv_bfloat16 h, l; split2(v, h, l);
        const size_t o = (size_t)(w0 + ty + i*8) * R + r0 + tx;
        ohb[o] = h; olb[o] = l;
    }
}

// ---------------- fused conv1x7 + RoPE + transpose-split (Q/K path) ----------------
__global__ __launch_bounds__(256) void convrope_k(
    const float* __restrict__ x, __nv_bfloat16* __restrict__ oh,
    __nv_bfloat16* __restrict__ ol,
    const float* __restrict__ wt, const float* __restrict__ bs)
{
    __shared__ float xin[2][32][40];
    __shared__ float cv[2][32][33];
    const int b = blockIdx.z;
    const int w0 = blockIdx.x*32, f0 = blockIdx.y*32;
    const int tx = threadIdx.x, ty = threadIdx.y;
    const int tid = ty*32 + tx;

    for (int i = tid; i < 2*32*38; i += 256) {
        const int ci = i / (32*38), rem = i % (32*38);
        const int fi = rem / 38, wi = rem % 38;
        const int wg = w0 + wi - 3;
        xin[ci][fi][wi] = ((unsigned)wg < (unsigned)Ww)
            ? x[((size_t)(b*2 + ci)*Ff + f0 + fi)*Ww + wg] : 0.f;
    }
    __syncthreads();

    float wreg[2][2][7];
    #pragma unroll
    for (int co = 0; co < 2; co++)
        #pragma unroll
        for (int ci = 0; ci < 2; ci++)
            #pragma unroll
            for (int j = 0; j < 7; j++)
                wreg[co][ci][j] = wt[(co*2 + ci)*7 + j];
    const float b0 = bs[0], b1 = bs[1];

    #pragma unroll
    for (int r = 0; r < 4; r++) {
        const int fi = ty*4 + r;
        float a0 = b0, a1 = b1;
        #pragma unroll
        for (int ci = 0; ci < 2; ci++)
            #pragma unroll
            for (int j = 0; j < 7; j++) {
                const float xv = xin[ci][fi][tx + j];
                a0 = fmaf(xv, wreg[0][ci][j], a0);
                a1 = fmaf(xv, wreg[1][ci][j], a1);
            }
        cv[0][fi][tx] = a0; cv[1][fi][tx] = a1;
    }
    __syncthreads();

    const int co = tid >> 7, wl = (tid >> 2) & 31, fq = (tid & 3) * 8;
    const int wg = w0 + wl;
    uint4 hv, lv;
    __nv_bfloat16* hb = (__nv_bfloat16*)&hv;
    __nv_bfloat16* lb = (__nv_bfloat16*)&lv;
    #pragma unroll
    for (int p = 0; p < 4; p++) {
        const int fl = fq + p*2;
        const float x0 = cv[co][fl][wl], x1 = cv[co][fl + 1][wl];
        const int fg = f0 + fl;
        const int ttp = (fg >> 1) & 127;
        const float inv = expf(-(float)ttp * (9.2103403719761836f / 128.f));
        float sn, cn; sincosf((float)wg * inv, &sn, &cn);
        const float y0 = x0*cn - x1*sn;
        const float y1 = x1*cn + x0*sn;
        split2(y0, hb[p*2],   lb[p*2]);
        split2(y1, hb[p*2+1], lb[p*2+1]);
    }
    const size_t o = ((size_t)(b*2 + co)*Ww + wg)*Ff + f0 + fq;
    *(uint4*)(oh + o) = hv;
    *(uint4*)(ol + o) = lv;
}

// ---------------- fused conv1x7 + split (V path), layout preserved ----------------
__global__ __launch_bounds__(256) void convsplit_k(
    const float* __restrict__ x, __nv_bfloat16* __restrict__ oh,
    __nv_bfloat16* __restrict__ ol,
    const float* __restrict__ wt, const float* __restrict__ bs)
{
    const int t = blockIdx.x * 256 + threadIdx.x;
    const int wc = t & 1023;
    const int f  = (t >> 10) & 1023;
    const int co = (t >> 20) & 1;
    const int bb = t >> 21;
    float s = bs[co];
    #pragma unroll
    for (int ci = 0; ci < Cc; ci++) {
        const float* row = x + ((size_t)(bb*Cc + ci) * Ff + f) * Ww;
        const float* wp  = wt + (co*Cc + ci) * 7;
        #pragma unroll
        for (int j = 0; j < 7; j++) {
            const int ww = wc + j - 3;
            if ((unsigned)ww < (unsigned)Ww) s = fmaf(row[ww], wp[j], s);
        }
    }
    __nv_bfloat16 h, l; split2(s, h, l);
    oh[t] = h; ol[t] = l;
}

// ---------------- conv 3x3 (pad 1), optional GELU ----------------
__global__ __launch_bounds__(256) void conv3x3_k(
    const float* __restrict__ x, float* __restrict__ y,
    const float* __restrict__ wt, const float* __restrict__ bs, int dogelu)
{
    const int t = blockIdx.x * 256 + threadIdx.x;
    const int wc = t & 1023;
    const int f  = (t >> 10) & 1023;
    const int co = (t >> 20) & 1;
    const int bb = t >> 21;
    float s = bs[co];
    #pragma unroll
    for (int ci = 0; ci < Cc; ci++) {
        const float* xp = x + ((size_t)(bb*Cc + ci)) * FW;
        const float* wp = wt + (co*Cc + ci) * 9;
        #pragma unroll
        for (int ky = 0; ky < 3; ky++) {
            const int ff = f + ky - 1;
            if ((unsigned)ff < (unsigned)Ff) {
                const float* row = xp + (size_t)ff * Ww;
                #pragma unroll
                for (int kx = 0; kx < 3; kx++) {
                    const int ww = wc + kx - 1;
                    if ((unsigned)ww < (unsigned)Ww) s = fmaf(row[ww], wp[ky*3+kx], s);
                }
            }
        }
    }
    if (dogelu) s = gelu_f(s);
    y[t] = s;
}

// ---------------- row softmax -> bf16 hi/lo ----------------
__global__ __launch_bounds__(256) void softmax_k(
    const float* __restrict__ sp, __nv_bfloat16* __restrict__ oh,
    __nv_bfloat16* __restrict__ ol)
{
    const size_t row = blockIdx.x;
    const float* p = sp + row * Ww;
    const int t = threadIdx.x, lane = t & 31, wid = t >> 5;
    float4 v = ((const float4*)p)[t];
    float mx = fmaxf(fmaxf(v.x, v.y), fmaxf(v.z, v.w));
    #pragma unroll
    for (int o = 16; o > 0; o >>= 1) mx = fmaxf(mx, __shfl_xor_sync(0xffffffffu, mx, o));
    __shared__ float red[8];
    if (lane == 0) red[wid] = mx;
    __syncthreads();
    mx = red[0];
    #pragma unroll
    for (int i = 1; i < 8; i++) mx = fmaxf(mx, red[i]);
    __syncthreads();
    v.x = expf(v.x - mx); v.y = expf(v.y - mx); v.z = expf(v.z - mx); v.w = expf(v.w - mx);
    float sm = v.x + v.y + v.z + v.w;
    #pragma unroll
    for (int o = 16; o > 0; o >>= 1) sm += __shfl_xor_sync(0xffffffffu, sm, o);
    if (lane == 0) red[wid] = sm;
    __syncthreads();
    sm = red[0]+red[1]+red[2]+red[3]+red[4]+red[5]+red[6]+red[7];
    const float r = 1.f / sm;
    v.x *= r; v.y *= r; v.z *= r; v.w *= r;
    __nv_bfloat162 h0, h1, l0, l1;
    split2(v.x, h0.x, l0.x); split2(v.y, h0.y, l0.y);
    split2(v.z, h1.x, l1.x); split2(v.w, h1.y, l1.y);
    ((__nv_bfloat162*)(oh + row*Ww))[t*2]   = h0;
    ((__nv_bfloat162*)(oh + row*Ww))[t*2+1] = h1;
    ((__nv_bfloat162*)(ol + row*Ww))[t*2]   = l0;
    ((__nv_bfloat162*)(ol + row*Ww))[t*2+1] = l1;
}

// ---------------- residual + LayerNorm over F, h <- LN(h+z), smem value cache ----------------
__global__ __launch_bounds__(512) void lnres_k(
    float* __restrict__ h, const float* __restrict__ z,
    const float* __restrict__ g, const float* __restrict__ b)
{
    extern __shared__ float val[];                  // [1024][32]
    const int tx = threadIdx.x, ty = threadIdx.y;
    const int wc = blockIdx.x * 32 + tx;
    const int bc = blockIdx.y;
    const int c  = bc & 1;
    float* hp = h + (size_t)bc * FW + wc;
    const float* zp = z + (size_t)bc * FW + wc;
    float sum = 0.f, sq = 0.f;
    for (int f = ty; f < Ff; f += 16) {
        const float v = hp[(size_t)f * Ww] + zp[(size_t)f * Ww];
        val[f*32 + tx] = v;
        sum += v; sq += v * v;
    }
    __shared__ float s1[16][32], s2[16][32];
    __shared__ float smu[32], srs[32];
    s1[ty][tx] = sum; s2[ty][tx] = sq;
    __syncthreads();
    if (ty == 0) {
        float a = 0.f, q = 0.f;
        #pragma unroll
        for (int r = 0; r < 16; r++) { a += s1[r][tx]; q += s2[r][tx]; }
        const float mu = a * (1.f / Ff);
        const float var = q * (1.f / Ff) - mu * mu;
        smu[tx] = mu; srs[tx] = rsqrtf(var + 1e-5f);
    }
    __syncthreads();
    const float mu = smu[tx], rs = srs[tx];
    for (int f = ty; f < Ff; f += 16) {
        const float v = val[f*32 + tx];
        hp[(size_t)f * Ww] = (v - mu) * rs * g[c*Ff + f] + b[c*Ff + f];
    }
}

// ---------------- 2-channel mix (1x1 conv / output projection) ----------------
__global__ __launch_bounds__(256) void chanmix_k(
    const float* __restrict__ in, float* __restrict__ out,
    const float* __restrict__ m, const float* __restrict__ bs)
{
    const int t = blockIdx.x * 256 + threadIdx.x;
    const int pos = t & (FW - 1);
    const int co  = (t >> 20) & 1;
    const int bb  = t >> 21;
    float s = bs ? bs[co] : 0.f;
    s = fmaf(in[(size_t)(bb*Cc + 0) * FW + pos], m[co*Cc + 0], s);
    s = fmaf(in[(size_t)(bb*Cc + 1) * FW + pos], m[co*Cc + 1], s);
    out[t] = s;
}

// ---------------- launch ----------------
extern "C" void kernel_launch(void* const* d_in, const int* in_sizes, int n_in,
                              void* d_out, int out_size)
{
    (void)in_sizes; (void)n_in; (void)out_size;
    const float* x       = (const float*)d_in[0];
    const float* enc_c1w = (const float*)d_in[1];
    const float* enc_c1b = (const float*)d_in[2];
    const float* enc_c2w = (const float*)d_in[3];
    const float* enc_c2b = (const float*)d_in[4];
    const float* enc_nw  = (const float*)d_in[5];
    const float* enc_nb  = (const float*)d_in[6];
    const float* qw  = (const float*)d_in[7];
    const float* qb  = (const float*)d_in[8];
    const float* qcw = (const float*)d_in[9];
    const float* qcb = (const float*)d_in[10];
    const float* kw  = (const float*)d_in[11];
    const float* kb  = (const float*)d_in[12];
    const float* kcw = (const float*)d_in[13];
    const float* kcb = (const float*)d_in[14];
    const float* vw  = (const float*)d_in[15];
    const float* vb  = (const float*)d_in[16];
    const float* vcw = (const float*)d_in[17];
    const float* vcb = (const float*)d_in[18];
    const float* ow  = (const float*)d_in[19];
    const float* ob  = (const float*)d_in[20];
    const float* ocw = (const float*)d_in[21];
    const float* ocb = (const float*)d_in[22];
    const float* n1w = (const float*)d_in[23];
    const float* n1b = (const float*)d_in[24];
    const float* f1w = (const float*)d_in[25];
    const float* f1b = (const float*)d_in[26];
    const float* f2w = (const float*)d_in[27];
    const float* f2b = (const float*)d_in[28];
    const float* n2w = (const float*)d_in[29];
    const float* n2b = (const float*)d_in[30];
    const float* out_w = (const float*)d_in[31];

    float *h, *t0, *t1, *s;
    __nv_bfloat16 *hTh,*hTl,*qTh,*qTl,*kTh,*kTl,*vh,*vl,*sh,*sl,*uTh,*uTl,*wh,*wl;
    cudaGetSymbolAddress((void**)&h,  g_h);
    cudaGetSymbolAddress((void**)&t0, g_t0);
    cudaGetSymbolAddress((void**)&t1, g_t1);
    cudaGetSymbolAddress((void**)&s,  g_s);
    cudaGetSymbolAddress((void**)&hTh, g_hTh); cudaGetSymbolAddress((void**)&hTl, g_hTl);
    cudaGetSymbolAddress((void**)&qTh, g_qTh); cudaGetSymbolAddress((void**)&qTl, g_qTl);
    cudaGetSymbolAddress((void**)&kTh, g_kTh); cudaGetSymbolAddress((void**)&kTl, g_kTl);
    cudaGetSymbolAddress((void**)&vh,  g_vh);  cudaGetSymbolAddress((void**)&vl,  g_vl);
    cudaGetSymbolAddress((void**)&sh,  g_sh);  cudaGetSymbolAddress((void**)&sl,  g_sl);
    cudaGetSymbolAddress((void**)&uTh, g_uTh); cudaGetSymbolAddress((void**)&uTl, g_uTl);
    cudaGetSymbolAddress((void**)&wh,  g_wh);  cudaGetSymbolAddress((void**)&wl,  g_wl);

    cudaFuncSetAttribute(tgemm_k<0,1,0>, cudaFuncAttributeMaxDynamicSharedMemorySize, TG_SMEM);
    cudaFuncSetAttribute(tgemm_k<0,0,0>, cudaFuncAttributeMaxDynamicSharedMemorySize, TG_SMEM);
    cudaFuncSetAttribute(tgemm_k<0,0,1>, cudaFuncAttributeMaxDynamicSharedMemorySize, TG_SMEM);
    cudaFuncSetAttribute(tgemm_k<1,1,2>, cudaFuncAttributeMaxDynamicSharedMemorySize, TG_SMEM);
    cudaFuncSetAttribute(lnres_k, cudaFuncAttributeMaxDynamicSharedMemorySize, 131072);

    const int EW = 16384;
    const dim3 LN_G(Ww/32, BC), LN_B(32, 16);
    const int BIG = 1 << 24;
    const dim3 CR_G(Ww/32, Ff/32, Bn), CR_B(32, 8);
    const dim3 ST_B(32, 8);
    const dim3 ST_F(Ww/32, Ff/32, BC);

    cudaMemcpyAsync(h, x, sizeof(float) * (size_t)BC * FW, cudaMemcpyDeviceToDevice, 0);

    // weight-style linear (fp32 out): C[bc, M, W] = W[c, M, K] @ XT[bc, W, K]^T + bias
    auto WG = [&](const __nv_bfloat16* Ah, const __nv_bfloat16* Al,
                  const __nv_bfloat16* Bh, const __nv_bfloat16* Bl,
                  float* Cx, const float* bias, int M, int K, long long cRow) {
        dim3 grid(Ww/128, M/128, BC);
        tgemm_k<0,1,0><<<grid,256,TG_SMEM>>>(Ah, Al, Bh, Bl, Cx, bias, nullptr, nullptr,
            K, K, K, Ww, 1, Cc, (long long)M*K, 0, (long long)Ww*K, 0,
            cRow, 0, (long long)M, 1.f);
    };

    // --------- FrameEncoder: 3 ResBlocks ---------
    for (int nb = 0; nb < NBn; nb++) {
        conv3x3_k<<<EW,256>>>(h,  t0, enc_c1w + nb*Cc*Cc*9, enc_c1b + nb*Cc, 1);
        conv3x3_k<<<EW,256>>>(t0, t1, enc_c2w + nb*Cc*Cc*9, enc_c2b + nb*Cc, 0);
        lnres_k<<<LN_G,LN_B,131072>>>(h, t1, enc_nw + nb*Cc*Ff, enc_nb + nb*Cc*Ff);
    }

    // --------- Transformer layers ---------
    for (int l = 0; l < Ll; l++) {
        const long long lwF = (long long)l * Cc * Ff * Ff;
        const long long lwE = (long long)l * Cc * EF * Ff;

        splitT_k<<<ST_F,ST_B>>>(h, hTh, hTl, Ff);   // [bc,W,F]

        // Q: linear -> fused conv1x7+rope+transpose-split
        split_k<<<2048,256>>>(qw + lwF, wh, wl, Cc*Ff*Ff/4);
        WG(wh, wl, hTh, hTl, t0, qb + l*Cc*Ff, Ff, Ff, (long long)FW);
        convrope_k<<<CR_G,CR_B>>>(t0, qTh, qTl, qcw + l*Cc*Cc*7, qcb + l*Cc);
        // K
        split_k<<<2048,256>>>(kw + lwF, wh, wl, Cc*Ff*Ff/4);
        WG(wh, wl, hTh, hTl, t0, kb + l*Cc*Ff, Ff, Ff, (long long)FW);
        convrope_k<<<CR_G,CR_B>>>(t0, kTh, kTl, kcw + l*Cc*Cc*7, kcb + l*Cc);
        // V: linear -> fused conv1x7+split (layout [F,W])
        split_k<<<2048,256>>>(vw + lwF, wh, wl, Cc*Ff*Ff/4);
        WG(wh, wl, hTh, hTl, t0, vb + l*Cc*Ff, Ff, Ff, (long long)FW);
        convsplit_k<<<EW,256>>>(t0, vh, vl, vcw + l*Cc*Cc*7, vcb + l*Cc);

        // scores[z=bc*4+h, q, k] = Q[q,:] . K[k,:] / 32
        tgemm_k<0,0,0><<<dim3(Ww/128, Ww/128, 16),256,TG_SMEM>>>(
            qTh, qTl, kTh, kTl, s, nullptr, nullptr, nullptr,
            Dd, Ff, Ff, Ww, Hh, BIG,
            (long long)FW, (long long)Dd, (long long)FW, (long long)Dd,
            4LL*WW, (long long)WW, 0, 0.03125f);
        softmax_k<<<16*1024,256>>>(s, sh, sl);
        // attnT[bc, q, h*256+d] -> bf16 split directly (reuse qT buffers)
        tgemm_k<0,0,1><<<dim3(Dd/128, Ww/128, 16),256,TG_SMEM>>>(
            sh, sl, vh, vl, nullptr, nullptr, qTh, qTl,
            Ww, Ww, Ww, Ff, Hh, BIG,
            4LL*WW, (long long)WW, (long long)FW, (long long)Dd*Ww,
            (long long)FW, (long long)Dd, 0, 1.f);

        // output projection + 1x1 channel conv + residual LN
        split_k<<<2048,256>>>(ow + lwF, wh, wl, Cc*Ff*Ff/4);
        WG(wh, wl, qTh, qTl, t1, ob + l*Cc*Ff, Ff, Ff, (long long)FW);
        chanmix_k<<<EW,256>>>(t1, t0, ocw + l*Cc*Cc, ocb + l*Cc);
        lnres_k<<<LN_G,LN_B,131072>>>(h, t0, n1w + l*Cc*Ff, n1b + l*Cc*Ff);

        // FFN: f1 writes transposed bf16 split directly (OUT=2, GELU)
        splitT_k<<<ST_F,ST_B>>>(h, hTh, hTl, Ff);
        split_k<<<8192,256>>>(f1w + lwE, wh, wl, Cc*EF*Ff/4);
        tgemm_k<1,1,2><<<dim3(Ww/128, EF/128, BC),256,TG_SMEM>>>(
            wh, wl, hTh, hTl, nullptr, f1b + l*Cc*EF, uTh, uTl,
            Ff, Ff, Ff, EF, 1, Cc,
            (long long)EF*Ff, 0, (long long)Ww*Ff, 0,
            (long long)Ww*EF, 0, (long long)EF, 1.f);
        split_k<<<8192,256>>>(f2w + lwE, wh, wl, Cc*Ff*EF/4);
        WG(wh, wl, uTh, uTl, t0, f2b + l*Cc*Ff, Ff, EF, (long long)FW);
        lnres_k<<<LN_G,LN_B,131072>>>(h, t0, n2w + l*Cc*Ff, n2b + l*Cc*Ff);
    }

    // --------- output channel mix ---------
    chanmix_k<<<EW,256>>>(h, (float*)d_out, out_w, nullptr);
}

// round 11
// speedup vs baseline: 1.3510x; 1.2913x over previous
#include <cuda_runtime.h>
#include <cuda_bf16.h>
#include <math.h>
#include <cstdint>

#define Bn 2
#define Cc 2
#define Ff 1024
#define Ww 1024
#define Hh 4
#define Dd 256
#define EF 4096
#define Ll 15
#define NBn 3
#define BC 4
#define FW (Ff*Ww)
#define WW (Ww*Ww)

// ---------------- scratch ----------------
__device__ float g_h [BC*FW];
__device__ float g_t0[BC*FW];
__device__ float g_t1[BC*FW];
__device__ float g_s [16*WW];                 // attention scores fp32
__device__ float g_hT[BC*FW];                 // [bc,W,F] tf32 operands
__device__ float g_qT[BC*FW];                 // [bc,W,F] (reused for attnT)
__device__ float g_kT[BC*FW];
__device__ float g_v [BC*FW];                 // [bc,F,W]
__device__ float g_sS[16*WW];                 // softmax probs tf32
__device__ float g_uT[(size_t)BC*Ww*EF];      // [bc,W,EF]
__device__ float g_w [(size_t)Cc*EF*Ff];      // weight cvt scratch

__device__ __forceinline__ float gelu_f(float x) {
    return 0.5f * x * (1.0f + erff(x * 0.70710678118654752f));
}
__device__ __forceinline__ float tf32r(float x){
    uint32_t u; asm("cvt.rna.tf32.f32 %0, %1;" : "=r"(u) : "f"(x));
    return __uint_as_float(u);
}

// ================= helpers =================
__device__ __forceinline__ uint32_t s2u(const void* p){
    uint32_t a;
    asm("{ .reg .u64 t; cvta.to.shared.u64 t, %1; cvt.u32.u64 %0, t; }" : "=r"(a) : "l"(p));
    return a;
}
__device__ __forceinline__ void cpa16(uint32_t dst, const void* src){
    asm volatile("cp.async.cg.shared.global [%0], [%1], 16;" :: "r"(dst), "l"(src));
}
__device__ __forceinline__ void cpa_commit(){ asm volatile("cp.async.commit_group;" ::: "memory"); }
template<int N> __device__ __forceinline__ void cpa_wait(){
    asm volatile("cp.async.wait_group %0;" :: "n"(N) : "memory");
}
__device__ __forceinline__ void ldm4(uint32_t& r0, uint32_t& r1, uint32_t& r2, uint32_t& r3, uint32_t a){
    asm volatile("ldmatrix.sync.aligned.m8n8.x4.shared.b16 {%0,%1,%2,%3}, [%4];"
                 : "=r"(r0), "=r"(r1), "=r"(r2), "=r"(r3) : "r"(a));
}
__device__ __forceinline__ void mma_tf32(float* c,
    uint32_t a0, uint32_t a1, uint32_t a2, uint32_t a3, uint32_t b0, uint32_t b1){
    asm volatile(
        "mma.sync.aligned.m16n8k8.row.col.f32.tf32.tf32.f32 "
        "{%0,%1,%2,%3}, {%4,%5,%6,%7}, {%8,%9}, {%0,%1,%2,%3};"
        : "+f"(c[0]), "+f"(c[1]), "+f"(c[2]), "+f"(c[3])
        : "r"(a0), "r"(a1), "r"(a2), "r"(a3), "r"(b0), "r"(b1));
}

// ================= TF32 tensor-core GEMM =================
// C[m,n] = scale * sum_k A(m,k)*B(n,k) (+bias[m]) (optional GELU)
// A,B fp32 (consumed as tf32), K-major rows. CTA tile 128x128, K chunk 64.
// OUT=0: fp32 to Cg. OUT=1: tf32-fp32 to CF (row-major). OUT=2: transposed to CF.
#define KC 64
#define STG_BYTES 65536u       // A 32K | B 32K
#define NSTG 3
#define TG_SMEM (3*65536 + 1024)

__device__ __forceinline__ void load_tiles(
    uint32_t sb, const float* pA, const float* pB,
    int m0, int n0, int k0, int lda, int ldb, int tid)
{
    #pragma unroll
    for (int it = 0; it < 8; it++) {
        const int slot = tid + it*256;          // 0..2047 : 128 rows x 16 chunks
        const int r = slot >> 4, c = slot & 15;
        const uint32_t sw = (uint32_t)(r*256) + (uint32_t)(((c ^ (r & 7))) << 4);
        cpa16(sb +     0 + sw, pA + (long long)(m0 + r)*lda + k0 + c*4);
        cpa16(sb + 32768 + sw, pB + (long long)(n0 + r)*ldb + k0 + c*4);
    }
}

template<int DOGELU, int HASBIAS, int OUT>
__global__ __launch_bounds__(256, 1) void tgemm_k(
    const float* __restrict__ Ag, const float* __restrict__ Bg,
    float* __restrict__ Cg, const float* __restrict__ biasg, float* __restrict__ CF,
    int K, int lda, int ldb, int ldc, int heads, int aMod,
    long long aSB, long long aSH, long long bSB, long long bSH,
    long long cSB, long long cSH, long long biasSB, float scale)
{
    extern __shared__ char dsm[];
    char* ap = (char*)(((uintptr_t)dsm + 1023) & ~(uintptr_t)1023);
    const uint32_t base = s2u(ap);
    const int tid = threadIdx.x;
    const int lane = tid & 31;
    const int wid = tid >> 5;
    const int wm = wid >> 2, wn = wid & 3;      // 2 x 4 warps, warp tile 64x32

    const int z = blockIdx.z, bb = z / heads, hh = z % heads;
    const float* pA = Ag + (long long)(bb % aMod)*aSB + (long long)hh*aSH;
    const float* pB = Bg + (long long)bb*bSB + (long long)hh*bSH;
    const long long cOff = (long long)bb*cSB + (long long)hh*cSH;
    const int m0 = blockIdx.y * 128;
    const int n0 = blockIdx.x * 128;

    float acc[4][4][4];
    #pragma unroll
    for (int i = 0; i < 4; i++)
        #pragma unroll
        for (int j = 0; j < 4; j++)
            #pragma unroll
            for (int r = 0; r < 4; r++) acc[i][j][r] = 0.f;

    const int NC = K / KC;
    const int NP = NC < NSTG ? NC : NSTG;
    for (int p = 0; p < NP; p++) {
        load_tiles(base + (uint32_t)p*STG_BYTES, pA, pB, m0, n0, p*KC, lda, ldb, tid);
        cpa_commit();
    }

    // ldmatrix addressing: tile = lane>>3, rowoff = (tile&1)*8 + (lane&7), chunk half = tile>>1
    const int ltile = lane >> 3;
    const int rowoff = (ltile & 1)*8 + (lane & 7);
    const int chalf = ltile >> 1;

    #pragma unroll 1
    for (int c = 0; c < NC; c++) {
        const uint32_t sb = base + (uint32_t)(c % NSTG) * STG_BYTES;
        const int rem = NC - 1 - c;
        if (rem >= 2) cpa_wait<2>(); else if (rem == 1) cpa_wait<1>(); else cpa_wait<0>();
        __syncthreads();

        #pragma unroll
        for (int kk = 0; kk < 8; kk++) {        // 8 k8 steps per 64-chunk
            const int cch = kk*2 + chalf;
            uint32_t a[4][4];
            #pragma unroll
            for (int mt = 0; mt < 4; mt++) {
                const int r = wm*64 + mt*16 + rowoff;
                const uint32_t ad = sb + (uint32_t)(r*256) + (uint32_t)((cch ^ (r & 7)) << 4);
                ldm4(a[mt][0], a[mt][1], a[mt][2], a[mt][3], ad);
            }
            uint32_t b[2][4];
            #pragma unroll
            for (int bt = 0; bt < 2; bt++) {
                const int r = wn*32 + bt*16 + rowoff;
                const uint32_t bd = sb + 32768 + (uint32_t)(r*256) + (uint32_t)((cch ^ (r & 7)) << 4);
                ldm4(b[bt][0], b[bt][1], b[bt][2], b[bt][3], bd);
            }
            #pragma unroll
            for (int mt = 0; mt < 4; mt++) {
                #pragma unroll
                for (int n8 = 0; n8 < 4; n8++) {
                    const int nt = n8 >> 1, j = n8 & 1;
                    mma_tf32(acc[mt][n8], a[mt][0], a[mt][1], a[mt][2], a[mt][3],
                             b[nt][j], b[nt][j+2]);
                }
            }
        }
        __syncthreads();
        if (c + NSTG < NC) {
            load_tiles(base + (uint32_t)(c % NSTG) * STG_BYTES, pA, pB,
                       m0, n0, (c + NSTG) * KC, lda, ldb, tid);
            cpa_commit();
        }
    }

    const float* bp = HASBIAS ? (biasg + (long long)(bb % aMod)*biasSB) : nullptr;

    if (OUT == 1 || OUT == 2) {
        __syncthreads();
        float* tb = (float*)ap;                 // OUT==1: [m][n] pad 132 ; OUT==2: [n][m] pad 132
        #pragma unroll
        for (int mt = 0; mt < 4; mt++) {
            const int r0l = wm*64 + mt*16 + (lane >> 2);
            const int r1l = r0l + 8;
            const float bv0 = HASBIAS ? bp[m0 + r0l] : 0.f;
            const float bv1 = HASBIAS ? bp[m0 + r1l] : 0.f;
            #pragma unroll
            for (int n8 = 0; n8 < 4; n8++) {
                const int cn = wn*32 + n8*8 + (lane & 3)*2;
                float v0 = acc[mt][n8][0]*scale + bv0;
                float v1 = acc[mt][n8][1]*scale + bv0;
                float v2 = acc[mt][n8][2]*scale + bv1;
                float v3 = acc[mt][n8][3]*scale + bv1;
                if (DOGELU) { v0 = gelu_f(v0); v1 = gelu_f(v1); v2 = gelu_f(v2); v3 = gelu_f(v3); }
                if (OUT == 2) {
                    tb[(cn  )*132 + r0l] = v0; tb[(cn+1)*132 + r0l] = v1;
                    tb[(cn  )*132 + r1l] = v2; tb[(cn+1)*132 + r1l] = v3;
                } else {
                    tb[r0l*132 + cn] = v0; tb[r0l*132 + cn + 1] = v1;
                    tb[r1l*132 + cn] = v2; tb[r1l*132 + cn + 1] = v3;
                }
            }
        }
        __syncthreads();
        #pragma unroll 1
        for (int r = wid; r < 128; r += 8) {
            float4 v = *(const float4*)(tb + r*132 + lane*4);
            v.x = tf32r(v.x); v.y = tf32r(v.y); v.z = tf32r(v.z); v.w = tf32r(v.w);
            long long o;
            if (OUT == 2) o = cOff + (long long)(n0 + r)*ldc + m0 + lane*4;
            else          o = cOff + (long long)(m0 + r)*ldc + n0 + lane*4;
            *(float4*)(CF + o) = v;
        }
        return;
    }

    #pragma unroll
    for (int mt = 0; mt < 4; mt++) {
        const int r0 = m0 + wm*64 + mt*16 + (lane >> 2);
        const int r1 = r0 + 8;
        const float bv0 = HASBIAS ? bp[r0] : 0.f;
        const float bv1 = HASBIAS ? bp[r1] : 0.f;
        #pragma unroll
        for (int n8 = 0; n8 < 4; n8++) {
            const int cn = n0 + wn*32 + n8*8 + (lane & 3)*2;
            float v0 = acc[mt][n8][0]*scale + bv0;
            float v1 = acc[mt][n8][1]*scale + bv0;
            float v2 = acc[mt][n8][2]*scale + bv1;
            float v3 = acc[mt][n8][3]*scale + bv1;
            if (DOGELU) { v0 = gelu_f(v0); v1 = gelu_f(v1); v2 = gelu_f(v2); v3 = gelu_f(v3); }
            *(float2*)&Cg[cOff + (long long)r0*ldc + cn] = make_float2(v0, v1);
            *(float2*)&Cg[cOff + (long long)r1*ldc + cn] = make_float2(v2, v3);
        }
    }
}

// ================= tf32-round copy =================
__global__ __launch_bounds__(256) void cast_k(
    const float* __restrict__ x, float* __restrict__ o, int n4)
{
    const int i = blockIdx.x * 256 + threadIdx.x;
    if (i >= n4) return;
    float4 v = ((const float4*)x)[i];
    v.x = tf32r(v.x); v.y = tf32r(v.y); v.z = tf32r(v.z); v.w = tf32r(v.w);
    ((float4*)o)[i] = v;
}

// transpose + tf32 round: [bc, R, W] -> [bc, W, R]
__global__ __launch_bounds__(256) void castT_k(
    const float* __restrict__ x, float* __restrict__ o, int R)
{
    __shared__ float t[32][33];
    const int bc = blockIdx.z;
    const int w0 = blockIdx.x * 32, r0 = blockIdx.y * 32;
    const int tx = threadIdx.x, ty = threadIdx.y;     // (32,8)
    const float* xb = x + (size_t)bc * R * Ww;
    #pragma unroll
    for (int i = 0; i < 4; i++)
        t[ty + i*8][tx] = xb[(size_t)(r0 + ty + i*8) * Ww + w0 + tx];
    __syncthreads();
    float* ob = o + (size_t)bc * Ww * R;
    #pragma unroll
    for (int i = 0; i < 4; i++)
        ob[(size_t)(w0 + ty + i*8) * R + r0 + tx] = tf32r(t[tx][ty + i*8]);
}

// ---------------- fused conv1x7 + RoPE + transpose (tf32 out) ----------------
__global__ __launch_bounds__(256) void convrope_k(
    const float* __restrict__ x, float* __restrict__ o,
    const float* __restrict__ wt, const float* __restrict__ bs)
{
    __shared__ float xin[2][32][40];
    __shared__ float cv[2][32][33];
    const int b = blockIdx.z;
    const int w0 = blockIdx.x*32, f0 = blockIdx.y*32;
    const int tx = threadIdx.x, ty = threadIdx.y;
    const int tid = ty*32 + tx;

    for (int i = tid; i < 2*32*38; i += 256) {
        const int ci = i / (32*38), rem = i % (32*38);
        const int fi = rem / 38, wi = rem % 38;
        const int wg = w0 + wi - 3;
        xin[ci][fi][wi] = ((unsigned)wg < (unsigned)Ww)
            ? x[((size_t)(b*2 + ci)*Ff + f0 + fi)*Ww + wg] : 0.f;
    }
    __syncthreads();

    float wreg[2][2][7];
    #pragma unroll
    for (int co = 0; co < 2; co++)
        #pragma unroll
        for (int ci = 0; ci < 2; ci++)
            #pragma unroll
            for (int j = 0; j < 7; j++)
                wreg[co][ci][j] = wt[(co*2 + ci)*7 + j];
    const float b0 = bs[0], b1 = bs[1];

    #pragma unroll
    for (int r = 0; r < 4; r++) {
        const int fi = ty*4 + r;
        float a0 = b0, a1 = b1;
        #pragma unroll
        for (int ci = 0; ci < 2; ci++)
            #pragma unroll
            for (int j = 0; j < 7; j++) {
                const float xv = xin[ci][fi][tx + j];
                a0 = fmaf(xv, wreg[0][ci][j], a0);
                a1 = fmaf(xv, wreg[1][ci][j], a1);
            }
        cv[0][fi][tx] = a0; cv[1][fi][tx] = a1;
    }
    __syncthreads();

    const int co = tid >> 7, wl = (tid >> 2) & 31, fq = (tid & 3) * 8;
    const int wg = w0 + wl;
    float ov[8];
    #pragma unroll
    for (int p = 0; p < 4; p++) {
        const int fl = fq + p*2;
        const float x0 = cv[co][fl][wl], x1 = cv[co][fl + 1][wl];
        const int fg = f0 + fl;
        const int ttp = (fg >> 1) & 127;
        const float inv = expf(-(float)ttp * (9.2103403719761836f / 128.f));
        float sn, cn; sincosf((float)wg * inv, &sn, &cn);
        ov[p*2]   = tf32r(x0*cn - x1*sn);
        ov[p*2+1] = tf32r(x1*cn + x0*sn);
    }
    float* op = o + ((size_t)(b*2 + co)*Ww + wg)*Ff + f0 + fq;
    *(float4*)(op)     = *(float4*)&ov[0];
    *(float4*)(op + 4) = *(float4*)&ov[4];
}

// ---------------- fused conv1x7 + tf32 cast (V path) ----------------
__global__ __launch_bounds__(256) void convcast_k(
    const float* __restrict__ x, float* __restrict__ o,
    const float* __restrict__ wt, const float* __restrict__ bs)
{
    const int t = blockIdx.x * 256 + threadIdx.x;
    const int wc = t & 1023;
    const int f  = (t >> 10) & 1023;
    const int co = (t >> 20) & 1;
    const int bb = t >> 21;
    float s = bs[co];
    #pragma unroll
    for (int ci = 0; ci < Cc; ci++) {
        const float* row = x + ((size_t)(bb*Cc + ci) * Ff + f) * Ww;
        const float* wp  = wt + (co*Cc + ci) * 7;
        #pragma unroll
        for (int j = 0; j < 7; j++) {
            const int ww = wc + j - 3;
            if ((unsigned)ww < (unsigned)Ww) s = fmaf(row[ww], wp[j], s);
        }
    }
    o[t] = tf32r(s);
}

// ---------------- conv 3x3 (pad 1), optional GELU ----------------
__global__ __launch_bounds__(256) void conv3x3_k(
    const float* __restrict__ x, float* __restrict__ y,
    const float* __restrict__ wt, const float* __restrict__ bs, int dogelu)
{
    const int t = blockIdx.x * 256 + threadIdx.x;
    const int wc = t & 1023;
    const int f  = (t >> 10) & 1023;
    const int co = (t >> 20) & 1;
    const int bb = t >> 21;
    float s = bs[co];
    #pragma unroll
    for (int ci = 0; ci < Cc; ci++) {
        const float* xp = x + ((size_t)(bb*Cc + ci)) * FW;
        const float* wp = wt + (co*Cc + ci) * 9;
        #pragma unroll
        for (int ky = 0; ky < 3; ky++) {
            const int ff = f + ky - 1;
            if ((unsigned)ff < (unsigned)Ff) {
                const float* row = xp + (size_t)ff * Ww;
                #pragma unroll
                for (int kx = 0; kx < 3; kx++) {
                    const int ww = wc + kx - 1;
                    if ((unsigned)ww < (unsigned)Ww) s = fmaf(row[ww], wp[ky*3+kx], s);
                }
            }
        }
    }
    if (dogelu) s = gelu_f(s);
    y[t] = s;
}

// ---------------- row softmax -> tf32 probs ----------------
__global__ __launch_bounds__(256) void softmax_k(
    const float* __restrict__ sp, float* __restrict__ o)
{
    const size_t row = blockIdx.x;
    const float* p = sp + row * Ww;
    const int t = threadIdx.x, lane = t & 31, wid = t >> 5;
    float4 v = ((const float4*)p)[t];
    float mx = fmaxf(fmaxf(v.x, v.y), fmaxf(v.z, v.w));
    #pragma unroll
    for (int ofs = 16; ofs > 0; ofs >>= 1) mx = fmaxf(mx, __shfl_xor_sync(0xffffffffu, mx, ofs));
    __shared__ float red[8];
    if (lane == 0) red[wid] = mx;
    __syncthreads();
    mx = red[0];
    #pragma unroll
    for (int i = 1; i < 8; i++) mx = fmaxf(mx, red[i]);
    __syncthreads();
    v.x = expf(v.x - mx); v.y = expf(v.y - mx); v.z = expf(v.z - mx); v.w = expf(v.w - mx);
    float sm = v.x + v.y + v.z + v.w;
    #pragma unroll
    for (int ofs = 16; ofs > 0; ofs >>= 1) sm += __shfl_xor_sync(0xffffffffu, sm, ofs);
    if (lane == 0) red[wid] = sm;
    __syncthreads();
    sm = red[0]+red[1]+red[2]+red[3]+red[4]+red[5]+red[6]+red[7];
    const float r = 1.f / sm;
    v.x = tf32r(v.x*r); v.y = tf32r(v.y*r); v.z = tf32r(v.z*r); v.w = tf32r(v.w*r);
    ((float4*)(o + row*Ww))[t] = v;
}

// ---------------- residual + LayerNorm over F ----------------
__global__ __launch_bounds__(512) void lnres_k(
    float* __restrict__ h, const float* __restrict__ z,
    const float* __restrict__ g, const float* __restrict__ b)
{
    extern __shared__ float val[];
    const int tx = threadIdx.x, ty = threadIdx.y;
    const int wc = blockIdx.x * 32 + tx;
    const int bc = blockIdx.y;
    const int c  = bc & 1;
    float* hp = h + (size_t)bc * FW + wc;
    const float* zp = z + (size_t)bc * FW + wc;
    float sum = 0.f, sq = 0.f;
    for (int f = ty; f < Ff; f += 16) {
        const float v = hp[(size_t)f * Ww] + zp[(size_t)f * Ww];
        val[f*32 + tx] = v;
        sum += v; sq += v * v;
    }
    __shared__ float s1[16][32], s2[16][32];
    __shared__ float smu[32], srs[32];
    s1[ty][tx] = sum; s2[ty][tx] = sq;
    __syncthreads();
    if (ty == 0) {
        float a = 0.f, q = 0.f;
        #pragma unroll
        for (int r = 0; r < 16; r++) { a += s1[r][tx]; q += s2[r][tx]; }
        const float mu = a * (1.f / Ff);
        const float var = q * (1.f / Ff) - mu * mu;
        smu[tx] = mu; srs[tx] = rsqrtf(var + 1e-5f);
    }
    __syncthreads();
    const float mu = smu[tx], rs = srs[tx];
    for (int f = ty; f < Ff; f += 16) {
        const float v = val[f*32 + tx];
        hp[(size_t)f * Ww] = (v - mu) * rs * g[c*Ff + f] + b[c*Ff + f];
    }
}

// ---------------- 2-channel mix ----------------
__global__ __launch_bounds__(256) void chanmix_k(
    const float* __restrict__ in, float* __restrict__ out,
    const float* __restrict__ m, const float* __restrict__ bs)
{
    const int t = blockIdx.x * 256 + threadIdx.x;
    const int pos = t & (FW - 1);
    const int co  = (t >> 20) & 1;
    const int bb  = t >> 21;
    float s = bs ? bs[co] : 0.f;
    s = fmaf(in[(size_t)(bb*Cc + 0) * FW + pos], m[co*Cc + 0], s);
    s = fmaf(in[(size_t)(bb*Cc + 1) * FW + pos], m[co*Cc + 1], s);
    out[t] = s;
}

// ---------------- launch ----------------
extern "C" void kernel_launch(void* const* d_in, const int* in_sizes, int n_in,
                              void* d_out, int out_size)
{
    (void)in_sizes; (void)n_in; (void)out_size;
    const float* x       = (const float*)d_in[0];
    const float* enc_c1w = (const float*)d_in[1];
    const float* enc_c1b = (const float*)d_in[2];
    const float* enc_c2w = (const float*)d_in[3];
    const float* enc_c2b = (const float*)d_in[4];
    const float* enc_nw  = (const float*)d_in[5];
    const float* enc_nb  = (const float*)d_in[6];
    const float* qw  = (const float*)d_in[7];
    const float* qb  = (const float*)d_in[8];
    const float* qcw = (const float*)d_in[9];
    const float* qcb = (const float*)d_in[10];
    const float* kw  = (const float*)d_in[11];
    const float* kb  = (const float*)d_in[12];
    const float* kcw = (const float*)d_in[13];
    const float* kcb = (const float*)d_in[14];
    const float* vw  = (const float*)d_in[15];
    const float* vb  = (const float*)d_in[16];
    const float* vcw = (const float*)d_in[17];
    const float* vcb = (const float*)d_in[18];
    const float* ow  = (const float*)d_in[19];
    const float* ob  = (const float*)d_in[20];
    const float* ocw = (const float*)d_in[21];
    const float* ocb = (const float*)d_in[22];
    const float* n1w = (const float*)d_in[23];
    const float* n1b = (const float*)d_in[24];
    const float* f1w = (const float*)d_in[25];
    const float* f1b = (const float*)d_in[26];
    const float* f2w = (const float*)d_in[27];
    const float* f2b = (const float*)d_in[28];
    const float* n2w = (const float*)d_in[29];
    const float* n2b = (const float*)d_in[30];
    const float* out_w = (const float*)d_in[31];

    float *h,*t0,*t1,*s,*hT,*qT,*kT,*v,*sS,*uT,*w;
    cudaGetSymbolAddress((void**)&h,  g_h);
    cudaGetSymbolAddress((void**)&t0, g_t0);
    cudaGetSymbolAddress((void**)&t1, g_t1);
    cudaGetSymbolAddress((void**)&s,  g_s);
    cudaGetSymbolAddress((void**)&hT, g_hT);
    cudaGetSymbolAddress((void**)&qT, g_qT);
    cudaGetSymbolAddress((void**)&kT, g_kT);
    cudaGetSymbolAddress((void**)&v,  g_v);
    cudaGetSymbolAddress((void**)&sS, g_sS);
    cudaGetSymbolAddress((void**)&uT, g_uT);
    cudaGetSymbolAddress((void**)&w,  g_w);

    cudaFuncSetAttribute(tgemm_k<0,1,0>, cudaFuncAttributeMaxDynamicSharedMemorySize, TG_SMEM);
    cudaFuncSetAttribute(tgemm_k<0,0,0>, cudaFuncAttributeMaxDynamicSharedMemorySize, TG_SMEM);
    cudaFuncSetAttribute(tgemm_k<0,0,1>, cudaFuncAttributeMaxDynamicSharedMemorySize, TG_SMEM);
    cudaFuncSetAttribute(tgemm_k<1,1,2>, cudaFuncAttributeMaxDynamicSharedMemorySize, TG_SMEM);
    cudaFuncSetAttribute(lnres_k, cudaFuncAttributeMaxDynamicSharedMemorySize, 131072);

    const int EW = 16384;
    const dim3 LN_G(Ww/32, BC), LN_B(32, 16);
    const int BIG = 1 << 24;
    const dim3 CR_G(Ww/32, Ff/32, Bn), CR_B(32, 8);
    const dim3 ST_B(32, 8);
    const dim3 ST_F(Ww/32, Ff/32, BC);

    cudaMemcpyAsync(h, x, sizeof(float) * (size_t)BC * FW, cudaMemcpyDeviceToDevice, 0);

    // weight-style linear (fp32 out): C[bc, M, W] = W[c, M, K] @ XT[bc, W, K]^T + bias
    auto WG = [&](const float* A, const float* B, float* Cx, const float* bias,
                  int M, int K, long long cRow) {
        dim3 grid(Ww/128, M/128, BC);
        tgemm_k<0,1,0><<<grid,256,TG_SMEM>>>(A, B, Cx, bias, nullptr,
            K, K, K, Ww, 1, Cc, (long long)M*K, 0, (long long)Ww*K, 0,
            cRow, 0, (long long)M, 1.f);
    };

    // --------- FrameEncoder ---------
    for (int nb = 0; nb < NBn; nb++) {
        conv3x3_k<<<EW,256>>>(h,  t0, enc_c1w + nb*Cc*Cc*9, enc_c1b + nb*Cc, 1);
        conv3x3_k<<<EW,256>>>(t0, t1, enc_c2w + nb*Cc*Cc*9, enc_c2b + nb*Cc, 0);
        lnres_k<<<LN_G,LN_B,131072>>>(h, t1, enc_nw + nb*Cc*Ff, enc_nb + nb*Cc*Ff);
    }

    // --------- Transformer layers ---------
    for (int l = 0; l < Ll; l++) {
        const long long lwF = (long long)l * Cc * Ff * Ff;
        const long long lwE = (long long)l * Cc * EF * Ff;

        castT_k<<<ST_F,ST_B>>>(h, hT, Ff);   // [bc,W,F] tf32

        // Q
        cast_k<<<2048,256>>>(qw + lwF, w, Cc*Ff*Ff/4);
        WG(w, hT, t0, qb + l*Cc*Ff, Ff, Ff, (long long)FW);
        convrope_k<<<CR_G,CR_B>>>(t0, qT, qcw + l*Cc*Cc*7, qcb + l*Cc);
        // K
        cast_k<<<2048,256>>>(kw + lwF, w, Cc*Ff*Ff/4);
        WG(w, hT, t0, kb + l*Cc*Ff, Ff, Ff, (long long)FW);
        convrope_k<<<CR_G,CR_B>>>(t0, kT, kcw + l*Cc*Cc*7, kcb + l*Cc);
        // V
        cast_k<<<2048,256>>>(vw + lwF, w, Cc*Ff*Ff/4);
        WG(w, hT, t0, vb + l*Cc*Ff, Ff, Ff, (long long)FW);
        convcast_k<<<EW,256>>>(t0, v, vcw + l*Cc*Cc*7, vcb + l*Cc);

        // scores = Q.K^T / 32  per (bc, head), K-dim = Dd
        tgemm_k<0,0,0><<<dim3(Ww/128, Ww/128, 16),256,TG_SMEM>>>(
            qT, kT, s, nullptr, nullptr,
            Dd, Ff, Ff, Ww, Hh, BIG,
            (long long)FW, (long long)Dd, (long long)FW, (long long)Dd,
            4LL*WW, (long long)WW, 0, 0.03125f);
        softmax_k<<<16*1024,256>>>(s, sS);
        // attnT[bc, q, h*256+d] (OUT=1 row-major into qT)
        tgemm_k<0,0,1><<<dim3(Dd/128, Ww/128, 16),256,TG_SMEM>>>(
            sS, v, nullptr, nullptr, qT,
            Ww, Ww, Ww, Ff, Hh, BIG,
            4LL*WW, (long long)WW, (long long)FW, (long long)Dd*Ww,
            (long long)FW, (long long)Dd, 0, 1.f);

        // output projection + 1x1 conv + residual LN
        cast_k<<<2048,256>>>(ow + lwF, w, Cc*Ff*Ff/4);
        WG(w, qT, t1, ob + l*Cc*Ff, Ff, Ff, (long long)FW);
        chanmix_k<<<EW,256>>>(t1, t0, ocw + l*Cc*Cc, ocb + l*Cc);
        lnres_k<<<LN_G,LN_B,131072>>>(h, t0, n1w + l*Cc*Ff, n1b + l*Cc*Ff);

        // FFN
        castT_k<<<ST_F,ST_B>>>(h, hT, Ff);
        cast_k<<<8192,256>>>(f1w + lwE, w, Cc*EF*Ff/4);
        tgemm_k<1,1,2><<<dim3(Ww/128, EF/128, BC),256,TG_SMEM>>>(
            w, hT, nullptr, f1b + l*Cc*EF, uT,
            Ff, Ff, Ff, EF, 1, Cc,
            (long long)EF*Ff, 0, (long long)Ww*Ff, 0,
            (long long)Ww*EF, 0, (long long)EF, 1.f);
        cast_k<<<8192,256>>>(f2w + lwE, w, Cc*Ff*EF/4);
        WG(w, uT, t0, f2b + l*Cc*Ff, Ff, EF, (long long)FW);
        lnres_k<<<LN_G,LN_B,131072>>>(h, t0, n2w + l*Cc*Ff, n2b + l*Cc*Ff);
    }

    // --------- output channel mix ---------
    chanmix_k<<<EW,256>>>(h, (float*)d_out, out_w, nullptr);
}